// round 1
// baseline (speedup 1.0000x reference)
#include <cuda_runtime.h>
#include <math.h>

// Problem constants
#define B_    8
#define LQ    512
#define LKV   2048
#define QDIM  768
#define KVDIM 768
#define HID   1024
#define NH    16
#define DH    64

// ---------------------------------------------------------------------------
// Scratch (device globals: no allocation allowed in kernel_launch)
// ---------------------------------------------------------------------------
__device__ float g_Q[(size_t)B_ * LQ * HID];     // 16 MB  projected Q  [B*Lq, HID]
__device__ float g_K[(size_t)B_ * LKV * HID];    // 64 MB  projected K  [B*Lkv, HID]
__device__ float g_V[(size_t)B_ * LKV * HID];    // 64 MB  projected V  [B*Lkv, HID]
__device__ float g_O[(size_t)B_ * LQ * HID];     // 16 MB  attention out [B*Lq, HID]
__device__ float g_bias[B_ * LKV];               // additive mask bias (0 or -1e30)
__device__ int   g_mask_kind;                    // 0=f32, 1=i32, 2=u8

// ---------------------------------------------------------------------------
// Mask dtype classification: scan first 16KB (safe lower bound for all
// plausible encodings of the 16384-element bool mask).
//   f32: words are 0x00000000 / 0x3f800000
//   i32: words are 0 / 1
//   u8 : bytes are 0 / 1 (fails both word tests almost surely for random mask)
// ---------------------------------------------------------------------------
__global__ void detect_mask_kind_kernel(const unsigned int* __restrict__ w) {
    __shared__ int bad_f32, bad_i32;
    if (threadIdx.x == 0) { bad_f32 = 0; bad_i32 = 0; }
    __syncthreads();
    int lf = 0, li = 0;
    for (int i = threadIdx.x; i < (B_ * LKV) / 4; i += blockDim.x) {  // 4096 words
        unsigned int x = w[i];
        if (!(x == 0u || x == 0x3f800000u)) lf = 1;
        if (!(x == 0u || x == 1u))          li = 1;
    }
    if (lf) bad_f32 = 1;
    if (li) bad_i32 = 1;
    __syncthreads();
    if (threadIdx.x == 0)
        g_mask_kind = (!bad_f32) ? 0 : ((!bad_i32) ? 1 : 2);
}

__global__ void build_bias_kernel(const void* __restrict__ mp) {
    int i = blockIdx.x * blockDim.x + threadIdx.x;
    if (i >= B_ * LKV) return;
    int k = g_mask_kind;
    bool on;
    if (k == 0)      on = (((const float*)mp)[i] != 0.0f);
    else if (k == 1) on = (((const int*)mp)[i] != 0);
    else             on = (((const unsigned char*)mp)[i] != 0);
    g_bias[i] = on ? 0.0f : -1.0e30f;
}

// ---------------------------------------------------------------------------
// SGEMM with bias:  C[M,N] = A[M,K] @ B[K,N] + bias[N]
// Block tile 128x128, K-tile 8, 256 threads, 8x8 register microtiles.
// Requires: M%128==0, N%128==0, K%8==0 (true for all call sites).
// ---------------------------------------------------------------------------
__global__ __launch_bounds__(256) void sgemm_bias(
    const float* __restrict__ A, const float* __restrict__ Bm,
    const float* __restrict__ bias, float* __restrict__ C,
    int M, int N, int K)
{
    __shared__ float As[8][128];
    __shared__ float Bs[8][128];

    const int tid  = threadIdx.x;
    const int bx   = blockIdx.x;   // N tile
    const int by   = blockIdx.y;   // M tile
    const int arow = tid >> 1;            // 0..127
    const int acol = (tid & 1) * 4;       // 0 or 4
    const int brow = tid >> 5;            // 0..7
    const int bcol = (tid & 31) * 4;      // 0..124
    const int tx   = tid & 15;
    const int ty   = tid >> 4;

    const float* Ap = A  + (size_t)(by * 128 + arow) * K + acol;
    const float* Bp = Bm + (size_t)brow * N + bx * 128 + bcol;

    float acc[8][8];
    #pragma unroll
    for (int i = 0; i < 8; i++)
        #pragma unroll
        for (int j = 0; j < 8; j++) acc[i][j] = 0.0f;

    for (int k0 = 0; k0 < K; k0 += 8) {
        float4 av = *(const float4*)(Ap + k0);
        float4 bv = *(const float4*)(Bp + (size_t)k0 * N);
        As[acol + 0][arow] = av.x;
        As[acol + 1][arow] = av.y;
        As[acol + 2][arow] = av.z;
        As[acol + 3][arow] = av.w;
        *(float4*)&Bs[brow][bcol] = bv;
        __syncthreads();

        #pragma unroll
        for (int k = 0; k < 8; k++) {
            float ra[8], rb[8];
            #pragma unroll
            for (int i = 0; i < 8; i++) ra[i] = As[k][ty * 8 + i];
            #pragma unroll
            for (int j = 0; j < 8; j++) rb[j] = Bs[k][tx * 8 + j];
            #pragma unroll
            for (int i = 0; i < 8; i++)
                #pragma unroll
                for (int j = 0; j < 8; j++)
                    acc[i][j] = fmaf(ra[i], rb[j], acc[i][j]);
        }
        __syncthreads();
    }

    const int row0 = by * 128 + ty * 8;
    const int col0 = bx * 128 + tx * 8;
    #pragma unroll
    for (int i = 0; i < 8; i++) {
        #pragma unroll
        for (int j = 0; j < 8; j += 4) {
            float4 o;
            o.x = acc[i][j + 0] + bias[col0 + j + 0];
            o.y = acc[i][j + 1] + bias[col0 + j + 1];
            o.z = acc[i][j + 2] + bias[col0 + j + 2];
            o.w = acc[i][j + 3] + bias[col0 + j + 3];
            *(float4*)&C[(size_t)(row0 + i) * N + col0 + j] = o;
        }
    }
}

// ---------------------------------------------------------------------------
// Fused attention (flash style) per (batch, head):
//   grid = (Lq/64, B*NH), 256 threads.
//   Q tile 64x64 kept in smem; loop over 32-row KV tiles with online softmax.
// Writes attention output directly in [B*Lq, HID] layout for the O-proj GEMM.
// ---------------------------------------------------------------------------
__global__ __launch_bounds__(256) void attn_kernel() {
    __shared__ float Qs[64][DH];          // 16 KB  (reads are warp-broadcast)
    __shared__ float KVs[32][DH + 1];     // K then V, padded
    __shared__ float Ps[64][33];          // scores -> probabilities, padded
    __shared__ float m_s[64], l_s[64], corr[64];

    const int bh  = blockIdx.y;
    const int b   = bh >> 4;
    const int h   = bh & 15;
    const int q0  = blockIdx.x * 64;
    const int tid = threadIdx.x;

    const float* Qg = g_Q + ((size_t)(b * LQ + q0)) * HID + h * DH;
    const float* Kg = g_K + ((size_t)b * LKV) * HID + h * DH;
    const float* Vg = g_V + ((size_t)b * LKV) * HID + h * DH;
    const float* bg = g_bias + b * LKV;

    // Load Q tile: 64 rows x 64 cols (row stride HID), 16 floats/thread
    {
        int r  = tid >> 2;             // 0..63
        int c0 = (tid & 3) * 16;       // 0,16,32,48
        const float* src = Qg + (size_t)r * HID + c0;
        #pragma unroll
        for (int t = 0; t < 4; t++) {
            float4 v = *(const float4*)(src + t * 4);
            *(float4*)&Qs[r][c0 + t * 4] = v;
        }
    }
    if (tid < 64) { m_s[tid] = -3.0e38f; l_s[tid] = 0.0f; }

    const int qy  = (tid >> 4) * 4;    // 4 q-rows per thread
    const int kx2 = (tid & 15) * 2;    // 2 kv-cols per thread (S phase)
    const int dx  = (tid & 15) * 4;    // 4 d-cols per thread (PV phase)

    float acc[4][4];
    #pragma unroll
    for (int i = 0; i < 4; i++)
        #pragma unroll
        for (int j = 0; j < 4; j++) acc[i][j] = 0.0f;

    __syncthreads();

    for (int j0 = 0; j0 < LKV; j0 += 32) {
        // ---- load K tile (32 x 64), 8 floats/thread ----
        {
            int r  = tid >> 3;             // 0..31
            int c0 = (tid & 7) * 8;        // 0..56
            const float* src = Kg + (size_t)(j0 + r) * HID + c0;
            float4 v0 = *(const float4*)(src);
            float4 v1 = *(const float4*)(src + 4);
            KVs[r][c0 + 0] = v0.x; KVs[r][c0 + 1] = v0.y;
            KVs[r][c0 + 2] = v0.z; KVs[r][c0 + 3] = v0.w;
            KVs[r][c0 + 4] = v1.x; KVs[r][c0 + 5] = v1.y;
            KVs[r][c0 + 6] = v1.z; KVs[r][c0 + 7] = v1.w;
        }
        __syncthreads();

        // ---- S = Q K^T (4x2 per thread) ----
        float s0[4], s1[4];
        #pragma unroll
        for (int i = 0; i < 4; i++) { s0[i] = 0.0f; s1[i] = 0.0f; }
        #pragma unroll 8
        for (int d = 0; d < DH; d++) {
            float k0v = KVs[kx2][d];
            float k1v = KVs[kx2 + 1][d];
            #pragma unroll
            for (int i = 0; i < 4; i++) {
                float qv = Qs[qy + i][d];
                s0[i] = fmaf(qv, k0v, s0[i]);
                s1[i] = fmaf(qv, k1v, s1[i]);
            }
        }
        {
            float bb0 = bg[j0 + kx2];
            float bb1 = bg[j0 + kx2 + 1];
            #pragma unroll
            for (int i = 0; i < 4; i++) {
                Ps[qy + i][kx2]     = fmaf(s0[i], 0.125f, bb0);  // scale = 1/sqrt(64)
                Ps[qy + i][kx2 + 1] = fmaf(s1[i], 0.125f, bb1);
            }
        }
        __syncthreads();

        // ---- online softmax (one thread per q row) + V tile load ----
        if (tid < 64) {
            float mold = m_s[tid];
            float mt = mold;
            #pragma unroll
            for (int c = 0; c < 32; c++) mt = fmaxf(mt, Ps[tid][c]);
            float cf = __expf(mold - mt);
            float lsum = 0.0f;
            #pragma unroll
            for (int c = 0; c < 32; c++) {
                float p = __expf(Ps[tid][c] - mt);
                Ps[tid][c] = p;
                lsum += p;
            }
            m_s[tid]  = mt;
            l_s[tid]  = l_s[tid] * cf + lsum;
            corr[tid] = cf;
        }
        {   // V load into the (now dead) K buffer — same phase as softmax
            int r  = tid >> 3;
            int c0 = (tid & 7) * 8;
            const float* src = Vg + (size_t)(j0 + r) * HID + c0;
            float4 v0 = *(const float4*)(src);
            float4 v1 = *(const float4*)(src + 4);
            KVs[r][c0 + 0] = v0.x; KVs[r][c0 + 1] = v0.y;
            KVs[r][c0 + 2] = v0.z; KVs[r][c0 + 3] = v0.w;
            KVs[r][c0 + 4] = v1.x; KVs[r][c0 + 5] = v1.y;
            KVs[r][c0 + 6] = v1.z; KVs[r][c0 + 7] = v1.w;
        }
        __syncthreads();

        // ---- rescale accumulators + O += P V (4x4 per thread) ----
        #pragma unroll
        for (int i = 0; i < 4; i++) {
            float cf = corr[qy + i];
            #pragma unroll
            for (int j = 0; j < 4; j++) acc[i][j] *= cf;
        }
        #pragma unroll 4
        for (int kv = 0; kv < 32; kv++) {
            float v0 = KVs[kv][dx + 0];
            float v1 = KVs[kv][dx + 1];
            float v2 = KVs[kv][dx + 2];
            float v3 = KVs[kv][dx + 3];
            #pragma unroll
            for (int i = 0; i < 4; i++) {
                float p = Ps[qy + i][kv];
                acc[i][0] = fmaf(p, v0, acc[i][0]);
                acc[i][1] = fmaf(p, v1, acc[i][1]);
                acc[i][2] = fmaf(p, v2, acc[i][2]);
                acc[i][3] = fmaf(p, v3, acc[i][3]);
            }
        }
        __syncthreads();   // protects KVs/Ps for next iteration
    }

    // ---- epilogue: divide by l, store in [B*Lq, HID] layout ----
    #pragma unroll
    for (int i = 0; i < 4; i++) {
        float inv = 1.0f / l_s[qy + i];
        float4 o;
        o.x = acc[i][0] * inv;
        o.y = acc[i][1] * inv;
        o.z = acc[i][2] * inv;
        o.w = acc[i][3] * inv;
        *(float4*)&g_O[(size_t)(b * LQ + q0 + qy + i) * HID + h * DH + dx] = o;
    }
}

// ---------------------------------------------------------------------------
// kernel_launch
// ---------------------------------------------------------------------------
extern "C" void kernel_launch(void* const* d_in, const int* in_sizes, int n_in,
                              void* d_out, int out_size) {
    (void)in_sizes; (void)n_in; (void)out_size;
    const float* query     = (const float*)d_in[0];   // [8,512,768]
    const float* key_value = (const float*)d_in[1];   // [8,2048,768]
    const void*  mask      = d_in[2];                 // [8,2048] bool-ish
    const float* Wq = (const float*)d_in[3];
    const float* bq = (const float*)d_in[4];
    const float* Wk = (const float*)d_in[5];
    const float* bk = (const float*)d_in[6];
    const float* Wv = (const float*)d_in[7];
    const float* bv = (const float*)d_in[8];
    const float* Wo = (const float*)d_in[9];
    const float* bo = (const float*)d_in[10];
    float* out = (float*)d_out;                        // [8,512,1024]

    float *Qp, *Kp, *Vp, *Op;
    cudaGetSymbolAddress((void**)&Qp, g_Q);
    cudaGetSymbolAddress((void**)&Kp, g_K);
    cudaGetSymbolAddress((void**)&Vp, g_V);
    cudaGetSymbolAddress((void**)&Op, g_O);

    // mask -> additive bias
    detect_mask_kind_kernel<<<1, 256>>>((const unsigned int*)mask);
    build_bias_kernel<<<(B_ * LKV + 255) / 256, 256>>>(mask);

    // projections
    dim3 gq(HID / 128, (B_ * LQ) / 128);    // (8, 32)
    dim3 gkv(HID / 128, (B_ * LKV) / 128);  // (8, 128)
    sgemm_bias<<<gq, 256>>>(query, Wq, bq, Qp, B_ * LQ, HID, QDIM);
    sgemm_bias<<<gkv, 256>>>(key_value, Wk, bk, Kp, B_ * LKV, HID, KVDIM);
    sgemm_bias<<<gkv, 256>>>(key_value, Wv, bv, Vp, B_ * LKV, HID, KVDIM);

    // fused attention
    attn_kernel<<<dim3(LQ / 64, B_ * NH), 256>>>();

    // output projection
    sgemm_bias<<<gq, 256>>>(Op, Wo, bo, out, B_ * LQ, HID, HID);
}

// round 3
// speedup vs baseline: 3.0732x; 3.0732x over previous
#include <cuda_runtime.h>
#include <math.h>
#include <stdint.h>

// Problem constants
#define B_    8
#define LQ    512
#define LKV   2048
#define QDIM  768
#define KVDIM 768
#define HID   1024
#define NH    16
#define DH    64

// ---------------------------------------------------------------------------
// Scratch (device globals: no allocation allowed in kernel_launch)
// ---------------------------------------------------------------------------
__device__ float g_Q[(size_t)B_ * LQ * HID];     // projected Q  [B*Lq, HID]
__device__ float g_K[(size_t)B_ * LKV * HID];    // projected K  [B*Lkv, HID]
__device__ float g_V[(size_t)B_ * LKV * HID];    // projected V  [B*Lkv, HID]
__device__ float g_O[(size_t)B_ * LQ * HID];     // attention out [B*Lq, HID]
__device__ float g_bias[B_ * LKV];               // additive mask bias (0 or -1e30)
__device__ int   g_mask_kind;                    // 0=f32, 1=i32, 2=u8

// ---------------------------------------------------------------------------
// tf32 helpers
// ---------------------------------------------------------------------------
__device__ __forceinline__ uint32_t f2tf(float x) {
    uint32_t r;
    asm("cvt.rna.tf32.f32 %0, %1;" : "=r"(r) : "f"(x));
    return r;
}
__device__ __forceinline__ float f2tf_f(float x) { return __uint_as_float(f2tf(x)); }

__device__ __forceinline__ void mma_tf32(float d[4], const uint32_t a[4],
                                         uint32_t b0, uint32_t b1) {
    asm volatile(
        "mma.sync.aligned.m16n8k8.row.col.f32.tf32.tf32.f32 "
        "{%0,%1,%2,%3}, {%4,%5,%6,%7}, {%8,%9}, {%0,%1,%2,%3};\n"
        : "+f"(d[0]), "+f"(d[1]), "+f"(d[2]), "+f"(d[3])
        : "r"(a[0]), "r"(a[1]), "r"(a[2]), "r"(a[3]), "r"(b0), "r"(b1));
}

// ---------------------------------------------------------------------------
// Mask dtype classification + bias build
// ---------------------------------------------------------------------------
__global__ void detect_mask_kind_kernel(const unsigned int* __restrict__ w) {
    __shared__ int bad_f32, bad_i32;
    if (threadIdx.x == 0) { bad_f32 = 0; bad_i32 = 0; }
    __syncthreads();
    int lf = 0, li = 0;
    for (int i = threadIdx.x; i < (B_ * LKV) / 4; i += blockDim.x) {
        unsigned int x = w[i];
        if (!(x == 0u || x == 0x3f800000u)) lf = 1;
        if (!(x == 0u || x == 1u))          li = 1;
    }
    if (lf) bad_f32 = 1;
    if (li) bad_i32 = 1;
    __syncthreads();
    if (threadIdx.x == 0)
        g_mask_kind = (!bad_f32) ? 0 : ((!bad_i32) ? 1 : 2);
}

__global__ void build_bias_kernel(const void* __restrict__ mp) {
    int i = blockIdx.x * blockDim.x + threadIdx.x;
    if (i >= B_ * LKV) return;
    int k = g_mask_kind;
    bool on;
    if (k == 0)      on = (((const float*)mp)[i] != 0.0f);
    else if (k == 1) on = (((const int*)mp)[i] != 0);
    else             on = (((const unsigned char*)mp)[i] != 0);
    g_bias[i] = on ? 0.0f : -1.0e30f;
}

// ---------------------------------------------------------------------------
// TF32 tensor-core GEMM with bias:  C[M,N] = A[M,K] @ B[K,N] + bias[N]
// Block tile 128x128, K-tile 32, 256 threads (8 warps, 2x4), warp tile 64x32.
// Static smem 35840 B. Requires M%128==0, N%128==0, K%32==0.
// ---------------------------------------------------------------------------
__global__ __launch_bounds__(256, 2) void sgemm_tf32(
    const float* __restrict__ A, const float* __restrict__ Bm,
    const float* __restrict__ bias, float* __restrict__ C,
    int M, int N, int K)
{
    __shared__ float As[128][36];   // [m][k]
    __shared__ float Bs[32][136];   // [k][n]

    const int tid  = threadIdx.x;
    const int lane = tid & 31;
    const int wid  = tid >> 5;
    const int g    = lane >> 2;     // groupID 0..7
    const int tig  = lane & 3;      // thread in group 0..3
    const int wm   = (wid >> 2) * 64;   // warp M offset (0 or 64)
    const int wn   = (wid & 3) * 32;    // warp N offset (0,32,64,96)
    const int bym  = blockIdx.y * 128;
    const int bxn  = blockIdx.x * 128;

    float acc[4][4][4];
    #pragma unroll
    for (int mi = 0; mi < 4; mi++)
        #pragma unroll
        for (int nj = 0; nj < 4; nj++)
            #pragma unroll
            for (int f = 0; f < 4; f++) acc[mi][nj][f] = 0.0f;

    for (int k0 = 0; k0 < K; k0 += 32) {
        // load A 128x32 (1024 float4, 4 per thread), convert to tf32
        #pragma unroll
        for (int i = 0; i < 4; i++) {
            int idx = tid + i * 256;
            int r = idx >> 3, c = (idx & 7) * 4;
            float4 v = *(const float4*)(A + (size_t)(bym + r) * K + k0 + c);
            v.x = f2tf_f(v.x); v.y = f2tf_f(v.y);
            v.z = f2tf_f(v.z); v.w = f2tf_f(v.w);
            *(float4*)&As[r][c] = v;
        }
        // load B 32x128
        #pragma unroll
        for (int i = 0; i < 4; i++) {
            int idx = tid + i * 256;
            int r = idx >> 5, c = (idx & 31) * 4;
            float4 v = *(const float4*)(Bm + (size_t)(k0 + r) * N + bxn + c);
            v.x = f2tf_f(v.x); v.y = f2tf_f(v.y);
            v.z = f2tf_f(v.z); v.w = f2tf_f(v.w);
            *(float4*)&Bs[r][c] = v;
        }
        __syncthreads();

        #pragma unroll
        for (int ks = 0; ks < 4; ks++) {
            const int kk = ks * 8;
            uint32_t af[4][4], bf[4][2];
            #pragma unroll
            for (int mi = 0; mi < 4; mi++) {
                int row = wm + mi * 16 + g;
                af[mi][0] = __float_as_uint(As[row][kk + tig]);
                af[mi][1] = __float_as_uint(As[row + 8][kk + tig]);
                af[mi][2] = __float_as_uint(As[row][kk + tig + 4]);
                af[mi][3] = __float_as_uint(As[row + 8][kk + tig + 4]);
            }
            #pragma unroll
            for (int nj = 0; nj < 4; nj++) {
                int col = wn + nj * 8 + g;
                bf[nj][0] = __float_as_uint(Bs[kk + tig][col]);
                bf[nj][1] = __float_as_uint(Bs[kk + tig + 4][col]);
            }
            #pragma unroll
            for (int mi = 0; mi < 4; mi++)
                #pragma unroll
                for (int nj = 0; nj < 4; nj++)
                    mma_tf32(acc[mi][nj], af[mi], bf[nj][0], bf[nj][1]);
        }
        __syncthreads();
    }

    // epilogue: + bias, float2 stores
    #pragma unroll
    for (int mi = 0; mi < 4; mi++) {
        int row = bym + wm + mi * 16 + g;
        #pragma unroll
        for (int nj = 0; nj < 4; nj++) {
            int col = bxn + wn + nj * 8 + 2 * tig;
            float b0 = bias[col], b1 = bias[col + 1];
            *(float2*)&C[(size_t)row * N + col] =
                make_float2(acc[mi][nj][0] + b0, acc[mi][nj][1] + b1);
            *(float2*)&C[(size_t)(row + 8) * N + col] =
                make_float2(acc[mi][nj][2] + b0, acc[mi][nj][3] + b1);
        }
    }
}

// ---------------------------------------------------------------------------
// Fused flash attention with tf32 tensor cores.  STATIC smem only (36352 B).
// grid = (LQ/128, B*NH), 256 threads (8 warps). Each warp owns 16 q-rows.
// Q fragments loaded straight from gmem to registers (one time).
// Per 32-row kv tile: S = Q K^T via mma, register softmax (quad shfl),
// P -> smem (warp-private rows), O += P V via mma.
// ---------------------------------------------------------------------------
#define PS_STR 36
#define KS_STR 68
#define VS_STR 72

__global__ __launch_bounds__(256) void attn_tf32() {
    __shared__ float Ps[128][PS_STR];   // probabilities (tf32-rounded)
    __shared__ float Ks[32][KS_STR];    // K tile
    __shared__ float Vs[32][VS_STR];    // V tile

    const int tid  = threadIdx.x;
    const int lane = tid & 31;
    const int w    = tid >> 5;      // warp 0..7 -> q rows w*16..w*16+15
    const int g    = lane >> 2;
    const int tig  = lane & 3;
    const int bh   = blockIdx.y;
    const int b    = bh >> 4;
    const int h    = bh & 15;
    const int q0   = blockIdx.x * 128;
    const int row0 = w * 16 + g;    // local q row (this thread also covers row0+8)

    const float* Qg = g_Q + ((size_t)(b * LQ + q0)) * HID + h * DH;
    const float* Kg = g_K + ((size_t)b * LKV) * HID + h * DH;
    const float* Vg = g_V + ((size_t)b * LKV) * HID + h * DH;
    const float* bg = g_bias + b * LKV;

    // ---- Q fragments straight from gmem (tf32-rounded), 8 k-steps over d=64
    uint32_t qf[8][4];
    {
        const float* q0p = Qg + (size_t)row0 * HID;
        const float* q8p = Qg + (size_t)(row0 + 8) * HID;
        #pragma unroll
        for (int kk = 0; kk < 8; kk++) {
            int col = kk * 8 + tig;
            qf[kk][0] = f2tf(q0p[col]);
            qf[kk][1] = f2tf(q8p[col]);
            qf[kk][2] = f2tf(q0p[col + 4]);
            qf[kk][3] = f2tf(q8p[col + 4]);
        }
    }

    float of[8][4];
    #pragma unroll
    for (int nj = 0; nj < 8; nj++)
        #pragma unroll
        for (int f = 0; f < 4; f++) of[nj][f] = 0.0f;
    float m0 = -1.0e30f, m1 = -1.0e30f, l0 = 0.0f, l1 = 0.0f;

    for (int j0 = 0; j0 < LKV; j0 += 32) {
        // ---- load K and V tiles (32x64 each), tf32-rounded ----
        // 512 float4 per tensor, 256 threads -> 2 float4 each
        #pragma unroll
        for (int i = 0; i < 2; i++) {
            int idx = tid + i * 256;
            int r = idx >> 4, c = (idx & 15) * 4;
            float4 kv = *(const float4*)(Kg + (size_t)(j0 + r) * HID + c);
            kv.x = f2tf_f(kv.x); kv.y = f2tf_f(kv.y);
            kv.z = f2tf_f(kv.z); kv.w = f2tf_f(kv.w);
            *(float4*)&Ks[r][c] = kv;
            float4 vv = *(const float4*)(Vg + (size_t)(j0 + r) * HID + c);
            vv.x = f2tf_f(vv.x); vv.y = f2tf_f(vv.y);
            vv.z = f2tf_f(vv.z); vv.w = f2tf_f(vv.w);
            *(float4*)&Vs[r][c] = vv;
        }
        __syncthreads();

        // ---- S = Q K^T : rows [w*16, w*16+16) x 32 kv cols ----
        float sv[4][4];
        #pragma unroll
        for (int nj = 0; nj < 4; nj++)
            #pragma unroll
            for (int f = 0; f < 4; f++) sv[nj][f] = 0.0f;
        #pragma unroll
        for (int kk = 0; kk < 8; kk++) {
            #pragma unroll
            for (int nj = 0; nj < 4; nj++) {
                uint32_t b0 = __float_as_uint(Ks[nj * 8 + g][kk * 8 + tig]);
                uint32_t b1 = __float_as_uint(Ks[nj * 8 + g][kk * 8 + tig + 4]);
                mma_tf32(sv[nj], qf[kk], b0, b1);
            }
        }

        // ---- scale + bias, online softmax in registers ----
        float mx0 = -1.0e30f, mx1 = -1.0e30f;
        #pragma unroll
        for (int nj = 0; nj < 4; nj++) {
            float2 bb = *(const float2*)&bg[j0 + nj * 8 + 2 * tig];
            sv[nj][0] = sv[nj][0] * 0.125f + bb.x;
            sv[nj][1] = sv[nj][1] * 0.125f + bb.y;
            sv[nj][2] = sv[nj][2] * 0.125f + bb.x;
            sv[nj][3] = sv[nj][3] * 0.125f + bb.y;
            mx0 = fmaxf(mx0, fmaxf(sv[nj][0], sv[nj][1]));
            mx1 = fmaxf(mx1, fmaxf(sv[nj][2], sv[nj][3]));
        }
        mx0 = fmaxf(mx0, __shfl_xor_sync(0xffffffffu, mx0, 1));
        mx0 = fmaxf(mx0, __shfl_xor_sync(0xffffffffu, mx0, 2));
        mx1 = fmaxf(mx1, __shfl_xor_sync(0xffffffffu, mx1, 1));
        mx1 = fmaxf(mx1, __shfl_xor_sync(0xffffffffu, mx1, 2));
        float mn0 = fmaxf(m0, mx0), mn1 = fmaxf(m1, mx1);
        float c0 = __expf(m0 - mn0), c1 = __expf(m1 - mn1);
        m0 = mn0; m1 = mn1;

        float sum0 = 0.0f, sum1 = 0.0f;
        #pragma unroll
        for (int nj = 0; nj < 4; nj++) {
            float p0 = __expf(sv[nj][0] - m0);
            float p1 = __expf(sv[nj][1] - m0);
            float p2 = __expf(sv[nj][2] - m1);
            float p3 = __expf(sv[nj][3] - m1);
            sum0 += p0 + p1;
            sum1 += p2 + p3;
            int col = nj * 8 + 2 * tig;
            Ps[row0][col]         = f2tf_f(p0);
            Ps[row0][col + 1]     = f2tf_f(p1);
            Ps[row0 + 8][col]     = f2tf_f(p2);
            Ps[row0 + 8][col + 1] = f2tf_f(p3);
        }
        sum0 += __shfl_xor_sync(0xffffffffu, sum0, 1);
        sum0 += __shfl_xor_sync(0xffffffffu, sum0, 2);
        sum1 += __shfl_xor_sync(0xffffffffu, sum1, 1);
        sum1 += __shfl_xor_sync(0xffffffffu, sum1, 2);
        l0 = l0 * c0 + sum0;
        l1 = l1 * c1 + sum1;

        // ---- rescale O accumulators ----
        #pragma unroll
        for (int nj = 0; nj < 8; nj++) {
            of[nj][0] *= c0; of[nj][1] *= c0;
            of[nj][2] *= c1; of[nj][3] *= c1;
        }

        // ---- O += P V (P warp-private rows; K-dim = 32 -> 4 k-steps) ----
        #pragma unroll
        for (int kk = 0; kk < 4; kk++) {
            uint32_t pf[4];
            int col = kk * 8 + tig;
            pf[0] = __float_as_uint(Ps[row0][col]);
            pf[1] = __float_as_uint(Ps[row0 + 8][col]);
            pf[2] = __float_as_uint(Ps[row0][col + 4]);
            pf[3] = __float_as_uint(Ps[row0 + 8][col + 4]);
            #pragma unroll
            for (int nj = 0; nj < 8; nj++) {
                uint32_t b0 = __float_as_uint(Vs[kk * 8 + tig][nj * 8 + g]);
                uint32_t b1 = __float_as_uint(Vs[kk * 8 + tig + 4][nj * 8 + g]);
                mma_tf32(of[nj], pf, b0, b1);
            }
        }
        __syncthreads();   // protect Ks/Vs before next tile's loads
    }

    // ---- epilogue: divide by l, store [B*Lq, HID] ----
    float inv0 = 1.0f / l0, inv1 = 1.0f / l1;
    #pragma unroll
    for (int nj = 0; nj < 8; nj++) {
        int col = nj * 8 + 2 * tig;
        float* dst = &g_O[(size_t)(b * LQ + q0 + row0) * HID + h * DH + col];
        *(float2*)dst = make_float2(of[nj][0] * inv0, of[nj][1] * inv0);
        *(float2*)(dst + (size_t)8 * HID) =
            make_float2(of[nj][2] * inv1, of[nj][3] * inv1);
    }
}

// ---------------------------------------------------------------------------
// kernel_launch
// ---------------------------------------------------------------------------
extern "C" void kernel_launch(void* const* d_in, const int* in_sizes, int n_in,
                              void* d_out, int out_size) {
    (void)in_sizes; (void)n_in; (void)out_size;
    const float* query     = (const float*)d_in[0];   // [8,512,768]
    const float* key_value = (const float*)d_in[1];   // [8,2048,768]
    const void*  mask      = d_in[2];                 // [8,2048] bool-ish
    const float* Wq = (const float*)d_in[3];
    const float* bq = (const float*)d_in[4];
    const float* Wk = (const float*)d_in[5];
    const float* bk = (const float*)d_in[6];
    const float* Wv = (const float*)d_in[7];
    const float* bv = (const float*)d_in[8];
    const float* Wo = (const float*)d_in[9];
    const float* bo = (const float*)d_in[10];
    float* out = (float*)d_out;                        // [8,512,1024]

    float *Qp, *Kp, *Vp, *Op;
    cudaGetSymbolAddress((void**)&Qp, g_Q);
    cudaGetSymbolAddress((void**)&Kp, g_K);
    cudaGetSymbolAddress((void**)&Vp, g_V);
    cudaGetSymbolAddress((void**)&Op, g_O);

    // mask -> additive bias
    detect_mask_kind_kernel<<<1, 256>>>((const unsigned int*)mask);
    build_bias_kernel<<<(B_ * LKV + 255) / 256, 256>>>(mask);

    // projections (tf32 tensor cores)
    dim3 gq(HID / 128, (B_ * LQ) / 128);    // (8, 32)
    dim3 gkv(HID / 128, (B_ * LKV) / 128);  // (8, 128)
    sgemm_tf32<<<gq, 256>>>(query, Wq, bq, Qp, B_ * LQ, HID, QDIM);
    sgemm_tf32<<<gkv, 256>>>(key_value, Wk, bk, Kp, B_ * LKV, HID, KVDIM);
    sgemm_tf32<<<gkv, 256>>>(key_value, Wv, bv, Vp, B_ * LKV, HID, KVDIM);

    // fused attention (tf32 tensor cores, static smem)
    attn_tf32<<<dim3(LQ / 128, B_ * NH), 256>>>();

    // output projection
    sgemm_tf32<<<gq, 256>>>(Op, Wo, bo, out, B_ * LQ, HID, HID);
}

// round 5
// speedup vs baseline: 3.4646x; 1.1274x over previous
#include <cuda_runtime.h>
#include <math.h>
#include <stdint.h>

// Problem constants
#define B_    8
#define LQ    512
#define LKV   2048
#define QDIM  768
#define KVDIM 768
#define HID   1024
#define NH    16
#define DH    64

// ---------------------------------------------------------------------------
// Scratch (device globals: no allocation allowed in kernel_launch)
// ---------------------------------------------------------------------------
__device__ float g_Q[(size_t)B_ * LQ * HID];      // projected Q (tf32-rounded)
__device__ float g_K[(size_t)B_ * LKV * HID];     // projected K (tf32-rounded)
__device__ float g_V[(size_t)B_ * LKV * HID];     // projected V (tf32-rounded)
__device__ float g_O[(size_t)B_ * LQ * HID];      // attention out (tf32-rounded)
__device__ float g_bias[B_ * LKV];                // additive mask bias
__device__ int   g_mask_kind;
// tf32-rounded copies of inputs (prep pass)
__device__ float g_Qr[(size_t)B_ * LQ * QDIM];
__device__ float g_KVr[(size_t)B_ * LKV * KVDIM];
__device__ float g_Wq[QDIM * HID];
__device__ float g_Wk[KVDIM * HID];
__device__ float g_Wv[KVDIM * HID];
__device__ float g_Wo[HID * HID];

// ---------------------------------------------------------------------------
// tf32 helpers
// ---------------------------------------------------------------------------
__device__ __forceinline__ uint32_t f2tf(float x) {
    uint32_t r;
    asm("cvt.rna.tf32.f32 %0, %1;" : "=r"(r) : "f"(x));
    return r;
}
__device__ __forceinline__ float f2tf_f(float x) { return __uint_as_float(f2tf(x)); }

__device__ __forceinline__ void mma_tf32(float d[4], const uint32_t a[4],
                                         uint32_t b0, uint32_t b1) {
    asm volatile(
        "mma.sync.aligned.m16n8k8.row.col.f32.tf32.tf32.f32 "
        "{%0,%1,%2,%3}, {%4,%5,%6,%7}, {%8,%9}, {%0,%1,%2,%3};\n"
        : "+f"(d[0]), "+f"(d[1]), "+f"(d[2]), "+f"(d[3])
        : "r"(a[0]), "r"(a[1]), "r"(a[2]), "r"(a[3]), "r"(b0), "r"(b1));
}

__device__ __forceinline__ void cp16(uint32_t dst_smem, const void* src) {
    asm volatile("cp.async.cg.shared.global [%0], [%1], 16;\n"
                 :: "r"(dst_smem), "l"(src));
}

// ---------------------------------------------------------------------------
// Prep: elementwise tf32 rounding copy (grid-stride, float4 granularity)
// ---------------------------------------------------------------------------
__global__ void round_copy(const float* __restrict__ s, float* __restrict__ d,
                           int n4) {
    for (int i = blockIdx.x * blockDim.x + threadIdx.x; i < n4;
         i += gridDim.x * blockDim.x) {
        float4 v = ((const float4*)s)[i];
        v.x = f2tf_f(v.x); v.y = f2tf_f(v.y);
        v.z = f2tf_f(v.z); v.w = f2tf_f(v.w);
        ((float4*)d)[i] = v;
    }
}

// ---------------------------------------------------------------------------
// Mask dtype classification + bias build
// ---------------------------------------------------------------------------
__global__ void detect_mask_kind_kernel(const unsigned int* __restrict__ w) {
    __shared__ int bad_f32, bad_i32;
    if (threadIdx.x == 0) { bad_f32 = 0; bad_i32 = 0; }
    __syncthreads();
    int lf = 0, li = 0;
    for (int i = threadIdx.x; i < (B_ * LKV) / 4; i += blockDim.x) {
        unsigned int x = w[i];
        if (!(x == 0u || x == 0x3f800000u)) lf = 1;
        if (!(x == 0u || x == 1u))          li = 1;
    }
    if (lf) bad_f32 = 1;
    if (li) bad_i32 = 1;
    __syncthreads();
    if (threadIdx.x == 0)
        g_mask_kind = (!bad_f32) ? 0 : ((!bad_i32) ? 1 : 2);
}

__global__ void build_bias_kernel(const void* __restrict__ mp) {
    int i = blockIdx.x * blockDim.x + threadIdx.x;
    if (i >= B_ * LKV) return;
    int k = g_mask_kind;
    bool on;
    if (k == 0)      on = (((const float*)mp)[i] != 0.0f);
    else if (k == 1) on = (((const int*)mp)[i] != 0);
    else             on = (((const unsigned char*)mp)[i] != 0);
    g_bias[i] = on ? 0.0f : -1.0e30f;
}

// ---------------------------------------------------------------------------
// Pipelined TF32 GEMM:  C[M,N] = A[M,K] @ B[K,N] + bias[N]
// A,B must be pre-rounded to tf32 values. 2-stage cp.async pipeline.
// Block tile 128x128, K-tile 16, 256 threads (8 warps, 2x4), warp tile 64x32.
// Static smem 37888 B. Requires M%128==0, N%128==0, K%16==0.
// round_out!=0 -> outputs rounded to tf32 values (for attention consumers).
// ---------------------------------------------------------------------------
#define LOAD_STAGE(s, k0)                                                     \
    do {                                                                      \
        cp16((uint32_t)__cvta_generic_to_shared(&As[s][ar0][ac0]),            \
             A + (size_t)(bym + ar0) * K + (k0) + ac0);                       \
        cp16((uint32_t)__cvta_generic_to_shared(&As[s][ar1][ac1]),            \
             A + (size_t)(bym + ar1) * K + (k0) + ac1);                       \
        cp16((uint32_t)__cvta_generic_to_shared(&Bs[s][br0][bc0]),            \
             Bm + (size_t)((k0) + br0) * N + bxn + bc0);                      \
        cp16((uint32_t)__cvta_generic_to_shared(&Bs[s][br1][bc1]),            \
             Bm + (size_t)((k0) + br1) * N + bxn + bc1);                      \
        asm volatile("cp.async.commit_group;\n" ::: "memory");                \
    } while (0)

__global__ __launch_bounds__(256, 2) void gemm_tf32_pipe(
    const float* __restrict__ A, const float* __restrict__ Bm,
    const float* __restrict__ bias, float* __restrict__ C,
    int M, int N, int K, int round_out)
{
    __shared__ float As[2][128][20];   // [stage][m][k], row stride 80 B
    __shared__ float Bs[2][16][136];   // [stage][k][n], row stride 544 B

    const int tid  = threadIdx.x;
    const int lane = tid & 31;
    const int wid  = tid >> 5;
    const int g    = lane >> 2;
    const int tig  = lane & 3;
    const int wm   = (wid >> 2) * 64;
    const int wn   = (wid & 3) * 32;
    const int bym  = blockIdx.y * 128;
    const int bxn  = blockIdx.x * 128;

    // per-thread load coordinates (2 chunks of 16B per tensor per stage)
    const int ar0 = tid >> 2,         ac0 = (tid & 3) * 4;
    const int ar1 = (tid + 256) >> 2, ac1 = ac0;
    const int br0 = tid >> 5,         bc0 = (tid & 31) * 4;
    const int br1 = (tid + 256) >> 5, bc1 = bc0;

    float acc[4][4][4];
    #pragma unroll
    for (int mi = 0; mi < 4; mi++)
        #pragma unroll
        for (int nj = 0; nj < 4; nj++)
            #pragma unroll
            for (int f = 0; f < 4; f++) acc[mi][nj][f] = 0.0f;

    const int T = K >> 4;
    LOAD_STAGE(0, 0);

    for (int t = 0; t < T; t++) {
        const int s = t & 1;
        if (t + 1 < T) {
            LOAD_STAGE(s ^ 1, (t + 1) << 4);
            asm volatile("cp.async.wait_group 1;\n" ::: "memory");
        } else {
            asm volatile("cp.async.wait_group 0;\n" ::: "memory");
        }
        __syncthreads();

        #pragma unroll
        for (int ks = 0; ks < 2; ks++) {
            const int kk = ks * 8;
            uint32_t af[4][4], bf[4][2];
            #pragma unroll
            for (int mi = 0; mi < 4; mi++) {
                int row = wm + mi * 16 + g;
                af[mi][0] = __float_as_uint(As[s][row][kk + tig]);
                af[mi][1] = __float_as_uint(As[s][row + 8][kk + tig]);
                af[mi][2] = __float_as_uint(As[s][row][kk + tig + 4]);
                af[mi][3] = __float_as_uint(As[s][row + 8][kk + tig + 4]);
            }
            #pragma unroll
            for (int nj = 0; nj < 4; nj++) {
                int col = wn + nj * 8 + g;
                bf[nj][0] = __float_as_uint(Bs[s][kk + tig][col]);
                bf[nj][1] = __float_as_uint(Bs[s][kk + tig + 4][col]);
            }
            #pragma unroll
            for (int mi = 0; mi < 4; mi++)
                #pragma unroll
                for (int nj = 0; nj < 4; nj++)
                    mma_tf32(acc[mi][nj], af[mi], bf[nj][0], bf[nj][1]);
        }
        __syncthreads();
    }

    // epilogue
    #pragma unroll
    for (int mi = 0; mi < 4; mi++) {
        int row = bym + wm + mi * 16 + g;
        #pragma unroll
        for (int nj = 0; nj < 4; nj++) {
            int col = bxn + wn + nj * 8 + 2 * tig;
            float b0 = bias[col], b1 = bias[col + 1];
            float v00 = acc[mi][nj][0] + b0, v01 = acc[mi][nj][1] + b1;
            float v10 = acc[mi][nj][2] + b0, v11 = acc[mi][nj][3] + b1;
            if (round_out) {
                v00 = f2tf_f(v00); v01 = f2tf_f(v01);
                v10 = f2tf_f(v10); v11 = f2tf_f(v11);
            }
            *(float2*)&C[(size_t)row * N + col] = make_float2(v00, v01);
            *(float2*)&C[(size_t)(row + 8) * N + col] = make_float2(v10, v11);
        }
    }
}

// ---------------------------------------------------------------------------
// Fused flash attention, tf32 tensor cores, static smem (36352 B).
// Inputs g_Q/g_K/g_V pre-rounded -> no cvt on loads. Register prefetch of the
// next 32-row KV tile overlaps gmem latency with compute.
// grid = (LQ/128, B*NH), 256 threads (8 warps), each warp owns 16 q-rows.
// ---------------------------------------------------------------------------
#define PS_STR 36
#define KS_STR 68
#define VS_STR 72

__global__ __launch_bounds__(256) void attn_tf32() {
    __shared__ float Ps[128][PS_STR];
    __shared__ float Ks[32][KS_STR];
    __shared__ float Vs[32][VS_STR];

    const int tid  = threadIdx.x;
    const int lane = tid & 31;
    const int w    = tid >> 5;
    const int g    = lane >> 2;
    const int tig  = lane & 3;
    const int bh   = blockIdx.y;
    const int b    = bh >> 4;
    const int h    = bh & 15;
    const int q0   = blockIdx.x * 128;
    const int row0 = w * 16 + g;

    const float* Qg = g_Q + ((size_t)(b * LQ + q0)) * HID + h * DH;
    const float* Kg = g_K + ((size_t)b * LKV) * HID + h * DH;
    const float* Vg = g_V + ((size_t)b * LKV) * HID + h * DH;
    const float* bg = g_bias + b * LKV;

    // per-thread KV tile coordinates (2 chunks of float4 per tensor)
    const int kr0 = tid >> 4,         kc0 = (tid & 15) * 4;
    const int kr1 = (tid + 256) >> 4, kc1 = kc0;

    // ---- Q fragments straight from gmem (already tf32 values) ----
    uint32_t qf[8][4];
    {
        const float* q0p = Qg + (size_t)row0 * HID;
        const float* q8p = Qg + (size_t)(row0 + 8) * HID;
        #pragma unroll
        for (int kk = 0; kk < 8; kk++) {
            int col = kk * 8 + tig;
            qf[kk][0] = __float_as_uint(q0p[col]);
            qf[kk][1] = __float_as_uint(q8p[col]);
            qf[kk][2] = __float_as_uint(q0p[col + 4]);
            qf[kk][3] = __float_as_uint(q8p[col + 4]);
        }
    }

    float of[8][4];
    #pragma unroll
    for (int nj = 0; nj < 8; nj++)
        #pragma unroll
        for (int f = 0; f < 4; f++) of[nj][f] = 0.0f;
    float m0 = -1.0e30f, m1 = -1.0e30f, l0 = 0.0f, l1 = 0.0f;

    // ---- prologue: prefetch tile 0 into registers ----
    float4 kreg0, kreg1, vreg0, vreg1;
    kreg0 = *(const float4*)(Kg + (size_t)kr0 * HID + kc0);
    kreg1 = *(const float4*)(Kg + (size_t)kr1 * HID + kc1);
    vreg0 = *(const float4*)(Vg + (size_t)kr0 * HID + kc0);
    vreg1 = *(const float4*)(Vg + (size_t)kr1 * HID + kc1);

    for (int j0 = 0; j0 < LKV; j0 += 32) {
        // commit prefetched tile to smem
        *(float4*)&Ks[kr0][kc0] = kreg0;
        *(float4*)&Ks[kr1][kc1] = kreg1;
        *(float4*)&Vs[kr0][kc0] = vreg0;
        *(float4*)&Vs[kr1][kc1] = vreg1;
        __syncthreads();

        // prefetch next tile (lands while we compute this one)
        if (j0 + 32 < LKV) {
            const float* kn = Kg + (size_t)(j0 + 32) * HID;
            const float* vn = Vg + (size_t)(j0 + 32) * HID;
            kreg0 = *(const float4*)(kn + (size_t)kr0 * HID + kc0);
            kreg1 = *(const float4*)(kn + (size_t)kr1 * HID + kc1);
            vreg0 = *(const float4*)(vn + (size_t)kr0 * HID + kc0);
            vreg1 = *(const float4*)(vn + (size_t)kr1 * HID + kc1);
        }

        // ---- S = Q K^T : rows [w*16, w*16+16) x 32 kv cols ----
        float sv[4][4];
        #pragma unroll
        for (int nj = 0; nj < 4; nj++)
            #pragma unroll
            for (int f = 0; f < 4; f++) sv[nj][f] = 0.0f;
        #pragma unroll
        for (int kk = 0; kk < 8; kk++) {
            #pragma unroll
            for (int nj = 0; nj < 4; nj++) {
                uint32_t b0 = __float_as_uint(Ks[nj * 8 + g][kk * 8 + tig]);
                uint32_t b1 = __float_as_uint(Ks[nj * 8 + g][kk * 8 + tig + 4]);
                mma_tf32(sv[nj], qf[kk], b0, b1);
            }
        }

        // ---- scale + bias, online softmax in registers ----
        float mx0 = -1.0e30f, mx1 = -1.0e30f;
        #pragma unroll
        for (int nj = 0; nj < 4; nj++) {
            float2 bb = *(const float2*)&bg[j0 + nj * 8 + 2 * tig];
            sv[nj][0] = sv[nj][0] * 0.125f + bb.x;
            sv[nj][1] = sv[nj][1] * 0.125f + bb.y;
            sv[nj][2] = sv[nj][2] * 0.125f + bb.x;
            sv[nj][3] = sv[nj][3] * 0.125f + bb.y;
            mx0 = fmaxf(mx0, fmaxf(sv[nj][0], sv[nj][1]));
            mx1 = fmaxf(mx1, fmaxf(sv[nj][2], sv[nj][3]));
        }
        mx0 = fmaxf(mx0, __shfl_xor_sync(0xffffffffu, mx0, 1));
        mx0 = fmaxf(mx0, __shfl_xor_sync(0xffffffffu, mx0, 2));
        mx1 = fmaxf(mx1, __shfl_xor_sync(0xffffffffu, mx1, 1));
        mx1 = fmaxf(mx1, __shfl_xor_sync(0xffffffffu, mx1, 2));
        float mn0 = fmaxf(m0, mx0), mn1 = fmaxf(m1, mx1);
        float c0 = __expf(m0 - mn0), c1 = __expf(m1 - mn1);
        m0 = mn0; m1 = mn1;

        float sum0 = 0.0f, sum1 = 0.0f;
        #pragma unroll
        for (int nj = 0; nj < 4; nj++) {
            float p0 = __expf(sv[nj][0] - m0);
            float p1 = __expf(sv[nj][1] - m0);
            float p2 = __expf(sv[nj][2] - m1);
            float p3 = __expf(sv[nj][3] - m1);
            sum0 += p0 + p1;
            sum1 += p2 + p3;
            int col = nj * 8 + 2 * tig;
            Ps[row0][col]         = f2tf_f(p0);
            Ps[row0][col + 1]     = f2tf_f(p1);
            Ps[row0 + 8][col]     = f2tf_f(p2);
            Ps[row0 + 8][col + 1] = f2tf_f(p3);
        }
        sum0 += __shfl_xor_sync(0xffffffffu, sum0, 1);
        sum0 += __shfl_xor_sync(0xffffffffu, sum0, 2);
        sum1 += __shfl_xor_sync(0xffffffffu, sum1, 1);
        sum1 += __shfl_xor_sync(0xffffffffu, sum1, 2);
        l0 = l0 * c0 + sum0;
        l1 = l1 * c1 + sum1;

        // ---- rescale O accumulators ----
        #pragma unroll
        for (int nj = 0; nj < 8; nj++) {
            of[nj][0] *= c0; of[nj][1] *= c0;
            of[nj][2] *= c1; of[nj][3] *= c1;
        }

        __syncwarp();   // P writes (smem) visible across the warp before PV

        // ---- O += P V (P warp-private rows; 4 k-steps over kv=32) ----
        #pragma unroll
        for (int kk = 0; kk < 4; kk++) {
            uint32_t pf[4];
            int col = kk * 8 + tig;
            pf[0] = __float_as_uint(Ps[row0][col]);
            pf[1] = __float_as_uint(Ps[row0 + 8][col]);
            pf[2] = __float_as_uint(Ps[row0][col + 4]);
            pf[3] = __float_as_uint(Ps[row0 + 8][col + 4]);
            #pragma unroll
            for (int nj = 0; nj < 8; nj++) {
                uint32_t b0 = __float_as_uint(Vs[kk * 8 + tig][nj * 8 + g]);
                uint32_t b1 = __float_as_uint(Vs[kk * 8 + tig + 4][nj * 8 + g]);
                mma_tf32(of[nj], pf, b0, b1);
            }
        }
        __syncthreads();   // all warps done with Ks/Vs before overwrite
    }

    // ---- epilogue: divide by l, round to tf32, store [B*Lq, HID] ----
    float inv0 = 1.0f / l0, inv1 = 1.0f / l1;
    #pragma unroll
    for (int nj = 0; nj < 8; nj++) {
        int col = nj * 8 + 2 * tig;
        float* dst = &g_O[(size_t)(b * LQ + q0 + row0) * HID + h * DH + col];
        *(float2*)dst = make_float2(f2tf_f(of[nj][0] * inv0),
                                    f2tf_f(of[nj][1] * inv0));
        *(float2*)(dst + (size_t)8 * HID) =
            make_float2(f2tf_f(of[nj][2] * inv1), f2tf_f(of[nj][3] * inv1));
    }
}

// ---------------------------------------------------------------------------
// kernel_launch
// ---------------------------------------------------------------------------
extern "C" void kernel_launch(void* const* d_in, const int* in_sizes, int n_in,
                              void* d_out, int out_size) {
    (void)in_sizes; (void)n_in; (void)out_size;
    const float* query     = (const float*)d_in[0];
    const float* key_value = (const float*)d_in[1];
    const void*  mask      = d_in[2];
    const float* Wq = (const float*)d_in[3];
    const float* bq = (const float*)d_in[4];
    const float* Wk = (const float*)d_in[5];
    const float* bk = (const float*)d_in[6];
    const float* Wv = (const float*)d_in[7];
    const float* bv = (const float*)d_in[8];
    const float* Wo = (const float*)d_in[9];
    const float* bo = (const float*)d_in[10];
    float* out = (float*)d_out;

    float *Qp, *Kp, *Vp, *Op, *Qr, *KVr, *Wqr, *Wkr, *Wvr, *Wor;
    cudaGetSymbolAddress((void**)&Qp,  g_Q);
    cudaGetSymbolAddress((void**)&Kp,  g_K);
    cudaGetSymbolAddress((void**)&Vp,  g_V);
    cudaGetSymbolAddress((void**)&Op,  g_O);
    cudaGetSymbolAddress((void**)&Qr,  g_Qr);
    cudaGetSymbolAddress((void**)&KVr, g_KVr);
    cudaGetSymbolAddress((void**)&Wqr, g_Wq);
    cudaGetSymbolAddress((void**)&Wkr, g_Wk);
    cudaGetSymbolAddress((void**)&Wvr, g_Wv);
    cudaGetSymbolAddress((void**)&Wor, g_Wo);

    // mask -> additive bias
    detect_mask_kind_kernel<<<1, 256>>>((const unsigned int*)mask);
    build_bias_kernel<<<(B_ * LKV + 255) / 256, 256>>>(mask);

    // prep: tf32-round all GEMM inputs once
    const int TPB = 256;
    int n4;
    n4 = (B_ * LQ * QDIM) / 4;
    round_copy<<<(n4 + TPB - 1) / TPB, TPB>>>(query, Qr, n4);
    n4 = (B_ * LKV * KVDIM) / 4;
    round_copy<<<(n4 + TPB - 1) / TPB, TPB>>>(key_value, KVr, n4);
    n4 = (QDIM * HID) / 4;
    round_copy<<<(n4 + TPB - 1) / TPB, TPB>>>(Wq, Wqr, n4);
    round_copy<<<(n4 + TPB - 1) / TPB, TPB>>>(Wk, Wkr, n4);
    round_copy<<<(n4 + TPB - 1) / TPB, TPB>>>(Wv, Wvr, n4);
    n4 = (HID * HID) / 4;
    round_copy<<<(n4 + TPB - 1) / TPB, TPB>>>(Wo, Wor, n4);

    // projections (pipelined tf32 GEMM), outputs rounded for attention
    dim3 gq(HID / 128, (B_ * LQ) / 128);
    dim3 gkv(HID / 128, (B_ * LKV) / 128);
    gemm_tf32_pipe<<<gq, 256>>>(Qr, Wqr, bq, Qp, B_ * LQ, HID, QDIM, 1);
    gemm_tf32_pipe<<<gkv, 256>>>(KVr, Wkr, bk, Kp, B_ * LKV, HID, KVDIM, 1);
    gemm_tf32_pipe<<<gkv, 256>>>(KVr, Wvr, bv, Vp, B_ * LKV, HID, KVDIM, 1);

    // fused attention
    attn_tf32<<<dim3(LQ / 128, B_ * NH), 256>>>();

    // output projection (full fp32 output)
    gemm_tf32_pipe<<<gq, 256>>>(Op, Wor, bo, out, B_ * LQ, HID, HID, 0);
}

// round 6
// speedup vs baseline: 3.4839x; 1.0056x over previous
#include <cuda_runtime.h>
#include <math.h>
#include <stdint.h>

// Problem constants
#define B_    8
#define LQ    512
#define LKV   2048
#define QDIM  768
#define KVDIM 768
#define HID   1024
#define NH    16
#define DH    64

// ---------------------------------------------------------------------------
// Scratch (device globals: no allocation allowed in kernel_launch)
// ---------------------------------------------------------------------------
__device__ float g_Q[(size_t)B_ * LQ * HID];      // projected Q (tf32-rounded)
__device__ float g_K[(size_t)B_ * LKV * HID];     // projected K (tf32-rounded)
__device__ float g_V[(size_t)B_ * LKV * HID];     // projected V (tf32-rounded)
__device__ float g_O[(size_t)B_ * LQ * HID];      // attention out (tf32-rounded)
__device__ float g_bias[B_ * LKV];                // additive mask bias
__device__ int   g_mask_kind;
// tf32-rounded copies of inputs (prep pass)
__device__ float g_Qr[(size_t)B_ * LQ * QDIM];
__device__ float g_KVr[(size_t)B_ * LKV * KVDIM];
__device__ float g_Wq[QDIM * HID];
__device__ float g_Wk[KVDIM * HID];
__device__ float g_Wv[KVDIM * HID];
__device__ float g_Wo[HID * HID];

// ---------------------------------------------------------------------------
// tf32 helpers
// ---------------------------------------------------------------------------
__device__ __forceinline__ uint32_t f2tf(float x) {
    uint32_t r;
    asm("cvt.rna.tf32.f32 %0, %1;" : "=r"(r) : "f"(x));
    return r;
}
__device__ __forceinline__ float f2tf_f(float x) { return __uint_as_float(f2tf(x)); }

__device__ __forceinline__ void mma_tf32(float d[4], const uint32_t a[4],
                                         uint32_t b0, uint32_t b1) {
    asm volatile(
        "mma.sync.aligned.m16n8k8.row.col.f32.tf32.tf32.f32 "
        "{%0,%1,%2,%3}, {%4,%5,%6,%7}, {%8,%9}, {%0,%1,%2,%3};\n"
        : "+f"(d[0]), "+f"(d[1]), "+f"(d[2]), "+f"(d[3])
        : "r"(a[0]), "r"(a[1]), "r"(a[2]), "r"(a[3]), "r"(b0), "r"(b1));
}

__device__ __forceinline__ void cp16(uint32_t dst_smem, const void* src) {
    asm volatile("cp.async.cg.shared.global [%0], [%1], 16;\n"
                 :: "r"(dst_smem), "l"(src));
}

// ---------------------------------------------------------------------------
// Prep: elementwise tf32 rounding copy (grid-stride, float4 granularity)
// ---------------------------------------------------------------------------
__global__ void round_copy(const float* __restrict__ s, float* __restrict__ d,
                           int n4) {
    for (int i = blockIdx.x * blockDim.x + threadIdx.x; i < n4;
         i += gridDim.x * blockDim.x) {
        float4 v = ((const float4*)s)[i];
        v.x = f2tf_f(v.x); v.y = f2tf_f(v.y);
        v.z = f2tf_f(v.z); v.w = f2tf_f(v.w);
        ((float4*)d)[i] = v;
    }
}

// ---------------------------------------------------------------------------
// Mask dtype classification + bias build
// ---------------------------------------------------------------------------
__global__ void detect_mask_kind_kernel(const unsigned int* __restrict__ w) {
    __shared__ int bad_f32, bad_i32;
    if (threadIdx.x == 0) { bad_f32 = 0; bad_i32 = 0; }
    __syncthreads();
    int lf = 0, li = 0;
    for (int i = threadIdx.x; i < (B_ * LKV) / 4; i += blockDim.x) {
        unsigned int x = w[i];
        if (!(x == 0u || x == 0x3f800000u)) lf = 1;
        if (!(x == 0u || x == 1u))          li = 1;
    }
    if (lf) bad_f32 = 1;
    if (li) bad_i32 = 1;
    __syncthreads();
    if (threadIdx.x == 0)
        g_mask_kind = (!bad_f32) ? 0 : ((!bad_i32) ? 1 : 2);
}

__global__ void build_bias_kernel(const void* __restrict__ mp) {
    int i = blockIdx.x * blockDim.x + threadIdx.x;
    if (i >= B_ * LKV) return;
    int k = g_mask_kind;
    bool on;
    if (k == 0)      on = (((const float*)mp)[i] != 0.0f);
    else if (k == 1) on = (((const int*)mp)[i] != 0);
    else             on = (((const unsigned char*)mp)[i] != 0);
    g_bias[i] = on ? 0.0f : -1.0e30f;
}

// ---------------------------------------------------------------------------
// Pipelined TF32 GEMM v2:  C[M,N] = A[M,K] @ B[K,N] + bias[N]
// A,B must be pre-rounded to tf32 values.
// Block tile 128x128, 128 threads (4 warps, 2x2), warp tile 64x64.
// 2-stage cp.async pipeline, K-tile 16, ONE __syncthreads per K-tile.
// Static smem 37888 B. Requires M%128==0, N%128==0, K%16==0.
// round_out!=0 -> outputs rounded to tf32 values (for attention consumers).
// ---------------------------------------------------------------------------
#define LOAD_STAGE(st, k0)                                                    \
    do {                                                                      \
        _Pragma("unroll")                                                     \
        for (int i = 0; i < 4; i++) {                                         \
            int idx = tid + i * 128;                                          \
            int r = idx >> 2, c = (idx & 3) * 4;                              \
            cp16((uint32_t)__cvta_generic_to_shared(&As[st][r][c]),           \
                 A + (size_t)(bym + r) * K + (k0) + c);                       \
        }                                                                     \
        _Pragma("unroll")                                                     \
        for (int i = 0; i < 4; i++) {                                         \
            int idx = tid + i * 128;                                          \
            int r = idx >> 5, c = (idx & 31) * 4;                             \
            cp16((uint32_t)__cvta_generic_to_shared(&Bs[st][r][c]),           \
                 Bm + (size_t)((k0) + r) * N + bxn + c);                      \
        }                                                                     \
        asm volatile("cp.async.commit_group;\n" ::: "memory");                \
    } while (0)

__global__ __launch_bounds__(128, 2) void gemm_tf32_pipe(
    const float* __restrict__ A, const float* __restrict__ Bm,
    const float* __restrict__ bias, float* __restrict__ C,
    int M, int N, int K, int round_out)
{
    __shared__ float As[2][128][20];   // [stage][m][k], row stride 80 B
    __shared__ float Bs[2][16][136];   // [stage][k][n], row stride 544 B

    const int tid  = threadIdx.x;
    const int lane = tid & 31;
    const int wid  = tid >> 5;          // 4 warps: 2x2
    const int g    = lane >> 2;
    const int tig  = lane & 3;
    const int wm   = (wid >> 1) * 64;   // warp M offset (0 or 64)
    const int wn   = (wid & 1) * 64;    // warp N offset (0 or 64)
    const int bym  = blockIdx.y * 128;
    const int bxn  = blockIdx.x * 128;

    float acc[4][8][4];
    #pragma unroll
    for (int mi = 0; mi < 4; mi++)
        #pragma unroll
        for (int nj = 0; nj < 8; nj++)
            #pragma unroll
            for (int f = 0; f < 4; f++) acc[mi][nj][f] = 0.0f;

    const int T = K >> 4;
    LOAD_STAGE(0, 0);

    for (int t = 0; t < T; t++) {
        const int s = t & 1;
        asm volatile("cp.async.wait_group 0;\n" ::: "memory");
        __syncthreads();   // stage s visible everywhere; all done with s^1
        if (t + 1 < T) LOAD_STAGE(s ^ 1, (t + 1) << 4);   // overlaps compute

        #pragma unroll
        for (int ks = 0; ks < 2; ks++) {
            const int kk = ks * 8;
            uint32_t af[4][4], bf[8][2];
            #pragma unroll
            for (int mi = 0; mi < 4; mi++) {
                int row = wm + mi * 16 + g;
                af[mi][0] = __float_as_uint(As[s][row][kk + tig]);
                af[mi][1] = __float_as_uint(As[s][row + 8][kk + tig]);
                af[mi][2] = __float_as_uint(As[s][row][kk + tig + 4]);
                af[mi][3] = __float_as_uint(As[s][row + 8][kk + tig + 4]);
            }
            #pragma unroll
            for (int nj = 0; nj < 8; nj++) {
                int col = wn + nj * 8 + g;
                bf[nj][0] = __float_as_uint(Bs[s][kk + tig][col]);
                bf[nj][1] = __float_as_uint(Bs[s][kk + tig + 4][col]);
            }
            #pragma unroll
            for (int mi = 0; mi < 4; mi++)
                #pragma unroll
                for (int nj = 0; nj < 8; nj++)
                    mma_tf32(acc[mi][nj], af[mi], bf[nj][0], bf[nj][1]);
        }
    }

    // epilogue
    #pragma unroll
    for (int mi = 0; mi < 4; mi++) {
        int row = bym + wm + mi * 16 + g;
        #pragma unroll
        for (int nj = 0; nj < 8; nj++) {
            int col = bxn + wn + nj * 8 + 2 * tig;
            float b0 = bias[col], b1 = bias[col + 1];
            float v00 = acc[mi][nj][0] + b0, v01 = acc[mi][nj][1] + b1;
            float v10 = acc[mi][nj][2] + b0, v11 = acc[mi][nj][3] + b1;
            if (round_out) {
                v00 = f2tf_f(v00); v01 = f2tf_f(v01);
                v10 = f2tf_f(v10); v11 = f2tf_f(v11);
            }
            *(float2*)&C[(size_t)row * N + col] = make_float2(v00, v01);
            *(float2*)&C[(size_t)(row + 8) * N + col] = make_float2(v10, v11);
        }
    }
}

// ---------------------------------------------------------------------------
// Fused flash attention, tf32 tensor cores, static smem (36352 B).
// Inputs g_Q/g_K/g_V pre-rounded -> no cvt on loads. Register prefetch of the
// next 32-row KV tile overlaps gmem latency with compute.
// grid = (LQ/128, B*NH), 256 threads (8 warps), each warp owns 16 q-rows.
// ---------------------------------------------------------------------------
#define PS_STR 36
#define KS_STR 68
#define VS_STR 72

__global__ __launch_bounds__(256) void attn_tf32() {
    __shared__ float Ps[128][PS_STR];
    __shared__ float Ks[32][KS_STR];
    __shared__ float Vs[32][VS_STR];

    const int tid  = threadIdx.x;
    const int lane = tid & 31;
    const int w    = tid >> 5;
    const int g    = lane >> 2;
    const int tig  = lane & 3;
    const int bh   = blockIdx.y;
    const int b    = bh >> 4;
    const int h    = bh & 15;
    const int q0   = blockIdx.x * 128;
    const int row0 = w * 16 + g;

    const float* Qg = g_Q + ((size_t)(b * LQ + q0)) * HID + h * DH;
    const float* Kg = g_K + ((size_t)b * LKV) * HID + h * DH;
    const float* Vg = g_V + ((size_t)b * LKV) * HID + h * DH;
    const float* bg = g_bias + b * LKV;

    // per-thread KV tile coordinates (2 chunks of float4 per tensor)
    const int kr0 = tid >> 4,         kc0 = (tid & 15) * 4;
    const int kr1 = (tid + 256) >> 4, kc1 = kc0;

    // ---- Q fragments straight from gmem (already tf32 values) ----
    uint32_t qf[8][4];
    {
        const float* q0p = Qg + (size_t)row0 * HID;
        const float* q8p = Qg + (size_t)(row0 + 8) * HID;
        #pragma unroll
        for (int kk = 0; kk < 8; kk++) {
            int col = kk * 8 + tig;
            qf[kk][0] = __float_as_uint(q0p[col]);
            qf[kk][1] = __float_as_uint(q8p[col]);
            qf[kk][2] = __float_as_uint(q0p[col + 4]);
            qf[kk][3] = __float_as_uint(q8p[col + 4]);
        }
    }

    float of[8][4];
    #pragma unroll
    for (int nj = 0; nj < 8; nj++)
        #pragma unroll
        for (int f = 0; f < 4; f++) of[nj][f] = 0.0f;
    float m0 = -1.0e30f, m1 = -1.0e30f, l0 = 0.0f, l1 = 0.0f;

    // ---- prologue: prefetch tile 0 into registers ----
    float4 kreg0, kreg1, vreg0, vreg1;
    kreg0 = *(const float4*)(Kg + (size_t)kr0 * HID + kc0);
    kreg1 = *(const float4*)(Kg + (size_t)kr1 * HID + kc1);
    vreg0 = *(const float4*)(Vg + (size_t)kr0 * HID + kc0);
    vreg1 = *(const float4*)(Vg + (size_t)kr1 * HID + kc1);

    for (int j0 = 0; j0 < LKV; j0 += 32) {
        // commit prefetched tile to smem
        *(float4*)&Ks[kr0][kc0] = kreg0;
        *(float4*)&Ks[kr1][kc1] = kreg1;
        *(float4*)&Vs[kr0][kc0] = vreg0;
        *(float4*)&Vs[kr1][kc1] = vreg1;
        __syncthreads();

        // prefetch next tile (lands while we compute this one)
        if (j0 + 32 < LKV) {
            const float* kn = Kg + (size_t)(j0 + 32) * HID;
            const float* vn = Vg + (size_t)(j0 + 32) * HID;
            kreg0 = *(const float4*)(kn + (size_t)kr0 * HID + kc0);
            kreg1 = *(const float4*)(kn + (size_t)kr1 * HID + kc1);
            vreg0 = *(const float4*)(vn + (size_t)kr0 * HID + kc0);
            vreg1 = *(const float4*)(vn + (size_t)kr1 * HID + kc1);
        }

        // ---- S = Q K^T : rows [w*16, w*16+16) x 32 kv cols ----
        float sv[4][4];
        #pragma unroll
        for (int nj = 0; nj < 4; nj++)
            #pragma unroll
            for (int f = 0; f < 4; f++) sv[nj][f] = 0.0f;
        #pragma unroll
        for (int kk = 0; kk < 8; kk++) {
            #pragma unroll
            for (int nj = 0; nj < 4; nj++) {
                uint32_t b0 = __float_as_uint(Ks[nj * 8 + g][kk * 8 + tig]);
                uint32_t b1 = __float_as_uint(Ks[nj * 8 + g][kk * 8 + tig + 4]);
                mma_tf32(sv[nj], qf[kk], b0, b1);
            }
        }

        // ---- scale + bias, online softmax in registers ----
        float mx0 = -1.0e30f, mx1 = -1.0e30f;
        #pragma unroll
        for (int nj = 0; nj < 4; nj++) {
            float2 bb = *(const float2*)&bg[j0 + nj * 8 + 2 * tig];
            sv[nj][0] = sv[nj][0] * 0.125f + bb.x;
            sv[nj][1] = sv[nj][1] * 0.125f + bb.y;
            sv[nj][2] = sv[nj][2] * 0.125f + bb.x;
            sv[nj][3] = sv[nj][3] * 0.125f + bb.y;
            mx0 = fmaxf(mx0, fmaxf(sv[nj][0], sv[nj][1]));
            mx1 = fmaxf(mx1, fmaxf(sv[nj][2], sv[nj][3]));
        }
        mx0 = fmaxf(mx0, __shfl_xor_sync(0xffffffffu, mx0, 1));
        mx0 = fmaxf(mx0, __shfl_xor_sync(0xffffffffu, mx0, 2));
        mx1 = fmaxf(mx1, __shfl_xor_sync(0xffffffffu, mx1, 1));
        mx1 = fmaxf(mx1, __shfl_xor_sync(0xffffffffu, mx1, 2));
        float mn0 = fmaxf(m0, mx0), mn1 = fmaxf(m1, mx1);
        float c0 = __expf(m0 - mn0), c1 = __expf(m1 - mn1);
        m0 = mn0; m1 = mn1;

        float sum0 = 0.0f, sum1 = 0.0f;
        #pragma unroll
        for (int nj = 0; nj < 4; nj++) {
            float p0 = __expf(sv[nj][0] - m0);
            float p1 = __expf(sv[nj][1] - m0);
            float p2 = __expf(sv[nj][2] - m1);
            float p3 = __expf(sv[nj][3] - m1);
            sum0 += p0 + p1;
            sum1 += p2 + p3;
            int col = nj * 8 + 2 * tig;
            Ps[row0][col]         = f2tf_f(p0);
            Ps[row0][col + 1]     = f2tf_f(p1);
            Ps[row0 + 8][col]     = f2tf_f(p2);
            Ps[row0 + 8][col + 1] = f2tf_f(p3);
        }
        sum0 += __shfl_xor_sync(0xffffffffu, sum0, 1);
        sum0 += __shfl_xor_sync(0xffffffffu, sum0, 2);
        sum1 += __shfl_xor_sync(0xffffffffu, sum1, 1);
        sum1 += __shfl_xor_sync(0xffffffffu, sum1, 2);
        l0 = l0 * c0 + sum0;
        l1 = l1 * c1 + sum1;

        // ---- rescale O accumulators ----
        #pragma unroll
        for (int nj = 0; nj < 8; nj++) {
            of[nj][0] *= c0; of[nj][1] *= c0;
            of[nj][2] *= c1; of[nj][3] *= c1;
        }

        __syncwarp();   // P writes (smem) visible across the warp before PV

        // ---- O += P V (P warp-private rows; 4 k-steps over kv=32) ----
        #pragma unroll
        for (int kk = 0; kk < 4; kk++) {
            uint32_t pf[4];
            int col = kk * 8 + tig;
            pf[0] = __float_as_uint(Ps[row0][col]);
            pf[1] = __float_as_uint(Ps[row0 + 8][col]);
            pf[2] = __float_as_uint(Ps[row0][col + 4]);
            pf[3] = __float_as_uint(Ps[row0 + 8][col + 4]);
            #pragma unroll
            for (int nj = 0; nj < 8; nj++) {
                uint32_t b0 = __float_as_uint(Vs[kk * 8 + tig][nj * 8 + g]);
                uint32_t b1 = __float_as_uint(Vs[kk * 8 + tig + 4][nj * 8 + g]);
                mma_tf32(of[nj], pf, b0, b1);
            }
        }
        __syncthreads();   // all warps done with Ks/Vs before overwrite
    }

    // ---- epilogue: divide by l, round to tf32, store [B*Lq, HID] ----
    float inv0 = 1.0f / l0, inv1 = 1.0f / l1;
    #pragma unroll
    for (int nj = 0; nj < 8; nj++) {
        int col = nj * 8 + 2 * tig;
        float* dst = &g_O[(size_t)(b * LQ + q0 + row0) * HID + h * DH + col];
        *(float2*)dst = make_float2(f2tf_f(of[nj][0] * inv0),
                                    f2tf_f(of[nj][1] * inv0));
        *(float2*)(dst + (size_t)8 * HID) =
            make_float2(f2tf_f(of[nj][2] * inv1), f2tf_f(of[nj][3] * inv1));
    }
}

// ---------------------------------------------------------------------------
// kernel_launch
// ---------------------------------------------------------------------------
extern "C" void kernel_launch(void* const* d_in, const int* in_sizes, int n_in,
                              void* d_out, int out_size) {
    (void)in_sizes; (void)n_in; (void)out_size;
    const float* query     = (const float*)d_in[0];
    const float* key_value = (const float*)d_in[1];
    const void*  mask      = d_in[2];
    const float* Wq = (const float*)d_in[3];
    const float* bq = (const float*)d_in[4];
    const float* Wk = (const float*)d_in[5];
    const float* bk = (const float*)d_in[6];
    const float* Wv = (const float*)d_in[7];
    const float* bv = (const float*)d_in[8];
    const float* Wo = (const float*)d_in[9];
    const float* bo = (const float*)d_in[10];
    float* out = (float*)d_out;

    float *Qp, *Kp, *Vp, *Op, *Qr, *KVr, *Wqr, *Wkr, *Wvr, *Wor;
    cudaGetSymbolAddress((void**)&Qp,  g_Q);
    cudaGetSymbolAddress((void**)&Kp,  g_K);
    cudaGetSymbolAddress((void**)&Vp,  g_V);
    cudaGetSymbolAddress((void**)&Op,  g_O);
    cudaGetSymbolAddress((void**)&Qr,  g_Qr);
    cudaGetSymbolAddress((void**)&KVr, g_KVr);
    cudaGetSymbolAddress((void**)&Wqr, g_Wq);
    cudaGetSymbolAddress((void**)&Wkr, g_Wk);
    cudaGetSymbolAddress((void**)&Wvr, g_Wv);
    cudaGetSymbolAddress((void**)&Wor, g_Wo);

    // mask -> additive bias
    detect_mask_kind_kernel<<<1, 256>>>((const unsigned int*)mask);
    build_bias_kernel<<<(B_ * LKV + 255) / 256, 256>>>(mask);

    // prep: tf32-round all GEMM inputs once
    const int TPB = 256;
    int n4;
    n4 = (B_ * LQ * QDIM) / 4;
    round_copy<<<(n4 + TPB - 1) / TPB, TPB>>>(query, Qr, n4);
    n4 = (B_ * LKV * KVDIM) / 4;
    round_copy<<<(n4 + TPB - 1) / TPB, TPB>>>(key_value, KVr, n4);
    n4 = (QDIM * HID) / 4;
    round_copy<<<(n4 + TPB - 1) / TPB, TPB>>>(Wq, Wqr, n4);
    round_copy<<<(n4 + TPB - 1) / TPB, TPB>>>(Wk, Wkr, n4);
    round_copy<<<(n4 + TPB - 1) / TPB, TPB>>>(Wv, Wvr, n4);
    n4 = (HID * HID) / 4;
    round_copy<<<(n4 + TPB - 1) / TPB, TPB>>>(Wo, Wor, n4);

    // projections (pipelined tf32 GEMM v2), outputs rounded for attention
    dim3 gq(HID / 128, (B_ * LQ) / 128);
    dim3 gkv(HID / 128, (B_ * LKV) / 128);
    gemm_tf32_pipe<<<gq, 128>>>(Qr, Wqr, bq, Qp, B_ * LQ, HID, QDIM, 1);
    gemm_tf32_pipe<<<gkv, 128>>>(KVr, Wkr, bk, Kp, B_ * LKV, HID, KVDIM, 1);
    gemm_tf32_pipe<<<gkv, 128>>>(KVr, Wvr, bv, Vp, B_ * LKV, HID, KVDIM, 1);

    // fused attention
    attn_tf32<<<dim3(LQ / 128, B_ * NH), 256>>>();

    // output projection (full fp32 output)
    gemm_tf32_pipe<<<gq, 128>>>(Op, Wor, bo, out, B_ * LQ, HID, HID, 0);
}

// round 10
// speedup vs baseline: 4.7875x; 1.3742x over previous
#include <cuda_runtime.h>
#include <cuda_fp16.h>
#include <math.h>
#include <stdint.h>

// Problem constants
#define B_    8
#define LQ    512
#define LKV   2048
#define QDIM  768
#define KVDIM 768
#define HID   1024
#define NH    16
#define DH    64

// ---------------------------------------------------------------------------
// Scratch (device globals)
// ---------------------------------------------------------------------------
__device__ float  g_Q[(size_t)B_ * LQ * HID];      // projected Q (tf32-rounded)
__device__ float  g_K[(size_t)B_ * LKV * HID];     // projected K (tf32-rounded)
__device__ float  g_V[(size_t)B_ * LKV * HID];     // projected V (tf32-rounded)
__device__ __half g_Oh[(size_t)B_ * LQ * HID];     // attention out (fp16)
__device__ float  g_bias[B_ * LKV];
__device__ int    g_mask_kind;
// fp16 prep buffers
__device__ __half g_Qh[(size_t)B_ * LQ * QDIM];    // query fp16 [M][K]
__device__ __half g_KVh[(size_t)B_ * LKV * KVDIM]; // key_value fp16 [M][K]
__device__ __half g_WqT[QDIM * HID];               // W^T fp16 [N][K]
__device__ __half g_WkT[KVDIM * HID];
__device__ __half g_WvT[KVDIM * HID];
__device__ __half g_WoT[HID * HID];

// ---------------------------------------------------------------------------
// Helpers
// ---------------------------------------------------------------------------
__device__ __forceinline__ uint32_t f2tf(float x) {
    uint32_t r;
    asm("cvt.rna.tf32.f32 %0, %1;" : "=r"(r) : "f"(x));
    return r;
}
__device__ __forceinline__ float f2tf_f(float x) { return __uint_as_float(f2tf(x)); }

__device__ __forceinline__ void mma_tf32(float d[4], const uint32_t a[4],
                                         uint32_t b0, uint32_t b1) {
    asm volatile(
        "mma.sync.aligned.m16n8k8.row.col.f32.tf32.tf32.f32 "
        "{%0,%1,%2,%3}, {%4,%5,%6,%7}, {%8,%9}, {%0,%1,%2,%3};\n"
        : "+f"(d[0]), "+f"(d[1]), "+f"(d[2]), "+f"(d[3])
        : "r"(a[0]), "r"(a[1]), "r"(a[2]), "r"(a[3]), "r"(b0), "r"(b1));
}

__device__ __forceinline__ void mma_f16(float d[4], const uint32_t a[4],
                                        uint32_t b0, uint32_t b1) {
    asm volatile(
        "mma.sync.aligned.m16n8k16.row.col.f32.f16.f16.f32 "
        "{%0,%1,%2,%3}, {%4,%5,%6,%7}, {%8,%9}, {%0,%1,%2,%3};\n"
        : "+f"(d[0]), "+f"(d[1]), "+f"(d[2]), "+f"(d[3])
        : "r"(a[0]), "r"(a[1]), "r"(a[2]), "r"(a[3]), "r"(b0), "r"(b1));
}

#define LDSM_X4(r, addr)                                                      \
    asm volatile("ldmatrix.sync.aligned.m8n8.x4.shared.b16 {%0,%1,%2,%3}, [%4];" \
                 : "=r"((r)[0]), "=r"((r)[1]), "=r"((r)[2]), "=r"((r)[3])     \
                 : "r"(addr))

__device__ __forceinline__ void cp16(uint32_t dst_smem, const void* src) {
    asm volatile("cp.async.cg.shared.global [%0], [%1], 16;\n"
                 :: "r"(dst_smem), "l"(src));
}

__device__ __forceinline__ uint32_t smem_u32(const void* p) {
    uint32_t a;
    asm("{ .reg .u64 t; cvta.to.shared.u64 t, %1; cvt.u32.u64 %0, t; }"
        : "=r"(a) : "l"(p));
    return a;
}

// ---------------------------------------------------------------------------
// Prep kernels
// ---------------------------------------------------------------------------
__global__ void to_half(const float* __restrict__ s, __half* __restrict__ d,
                        int n4) {
    for (int i = blockIdx.x * blockDim.x + threadIdx.x; i < n4;
         i += gridDim.x * blockDim.x) {
        float4 v = ((const float4*)s)[i];
        ((__half2*)d)[i * 2]     = __floats2half2_rn(v.x, v.y);
        ((__half2*)d)[i * 2 + 1] = __floats2half2_rn(v.z, v.w);
    }
}

// W[K][N] fp32 -> WT[N][K] fp16. block (32,8), grid (N/32, K/32).
__global__ void transpose_half(const float* __restrict__ s,
                               __half* __restrict__ d, int K, int N) {
    __shared__ float t[32][33];
    int n0 = blockIdx.x * 32, k0 = blockIdx.y * 32;
    int tx = threadIdx.x, ty = threadIdx.y;
    #pragma unroll
    for (int i = 0; i < 32; i += 8)
        t[ty + i][tx] = s[(size_t)(k0 + ty + i) * N + n0 + tx];
    __syncthreads();
    #pragma unroll
    for (int i = 0; i < 32; i += 8)
        d[(size_t)(n0 + ty + i) * K + k0 + tx] = __float2half(t[tx][ty + i]);
}

// ---------------------------------------------------------------------------
// Mask dtype classification + bias build
// ---------------------------------------------------------------------------
__global__ void detect_mask_kind_kernel(const unsigned int* __restrict__ w) {
    __shared__ int bad_f32, bad_i32;
    if (threadIdx.x == 0) { bad_f32 = 0; bad_i32 = 0; }
    __syncthreads();
    int lf = 0, li = 0;
    for (int i = threadIdx.x; i < (B_ * LKV) / 4; i += blockDim.x) {
        unsigned int x = w[i];
        if (!(x == 0u || x == 0x3f800000u)) lf = 1;
        if (!(x == 0u || x == 1u))          li = 1;
    }
    if (lf) bad_f32 = 1;
    if (li) bad_i32 = 1;
    __syncthreads();
    if (threadIdx.x == 0)
        g_mask_kind = (!bad_f32) ? 0 : ((!bad_i32) ? 1 : 2);
}

__global__ void build_bias_kernel(const void* __restrict__ mp) {
    int i = blockIdx.x * blockDim.x + threadIdx.x;
    if (i >= B_ * LKV) return;
    int k = g_mask_kind;
    bool on;
    if (k == 0)      on = (((const float*)mp)[i] != 0.0f);
    else if (k == 1) on = (((const int*)mp)[i] != 0);
    else             on = (((const unsigned char*)mp)[i] != 0);
    g_bias[i] = on ? 0.0f : -1.0e30f;
}

// ---------------------------------------------------------------------------
// FP16 tensor-core GEMM:  C[M,N] = A[M,K] @ BT[N,K]^T + bias[N]  (f32 accum)
// A, BT fp16. Block 128x128, 256 threads (8 warps, 2Mx4N), warp 64x32.
// K-tile 32 halves (64B rows). 2-stage cp.async, single sync/iter.
// ldmatrix fragment loads; smem row stride 80 B (conflict-free LDSM).
// round_out!=0 -> outputs rounded to tf32 values (attention consumes raw).
// ---------------------------------------------------------------------------
#define GSTAGE 10240   // 128 rows * 80 B

#define LOAD_F16(st, k0)                                                      \
    do {                                                                      \
        _Pragma("unroll")                                                     \
        for (int i = 0; i < 2; i++) {                                         \
            int idx = tid + i * 256;                                          \
            int r = idx >> 2, c = idx & 3;                                    \
            cp16(saA + (st) * GSTAGE + r * 80 + c * 16,                       \
                 A + (size_t)(bym + r) * K + (k0) + c * 8);                   \
            cp16(saB + (st) * GSTAGE + r * 80 + c * 16,                       \
                 BT + (size_t)(bxn + r) * K + (k0) + c * 8);                  \
        }                                                                     \
        asm volatile("cp.async.commit_group;\n" ::: "memory");                \
    } while (0)

__global__ __launch_bounds__(256, 2) void gemm_f16(
    const __half* __restrict__ A, const __half* __restrict__ BT,
    const float* __restrict__ bias, float* __restrict__ C,
    int M, int N, int K, int round_out)
{
    __shared__ __align__(16) __half As[2][128][40];
    __shared__ __align__(16) __half Bs[2][128][40];

    const int tid  = threadIdx.x;
    const int lane = tid & 31;
    const int wid  = tid >> 5;
    const int g    = lane >> 2;
    const int tig  = lane & 3;
    const int wm   = (wid >> 2) * 64;
    const int wn   = (wid & 3) * 32;
    const int bym  = blockIdx.y * 128;
    const int bxn  = blockIdx.x * 128;

    const uint32_t saA = smem_u32(&As[0][0][0]);
    const uint32_t saB = smem_u32(&Bs[0][0][0]);

    // per-lane ldmatrix address bases (x4 address groups)
    const int lr  = lane & 7;
    const int seg = lane >> 3;
    // A: m0=a0(row lr,k lo) m1=a1(+8,lo) m2=a2(lr,hi) m3=a3(+8,hi)
    const uint32_t aOff = (uint32_t)(wm + lr + (seg & 1) * 8) * 80
                        + ((seg >> 1) & 1) * 16;
    // B: m0=b0(nj even) m1=b1(nj even) m2=b0(nj odd) m3=b1(nj odd)
    const uint32_t bOff = (uint32_t)(wn + lr + ((seg >> 1) & 1) * 8) * 80
                        + (seg & 1) * 16;

    float acc[4][4][4];
    #pragma unroll
    for (int mi = 0; mi < 4; mi++)
        #pragma unroll
        for (int nj = 0; nj < 4; nj++)
            #pragma unroll
            for (int f = 0; f < 4; f++) acc[mi][nj][f] = 0.0f;

    const int T = K >> 5;   // K-tiles of 32 halves
    LOAD_F16(0, 0);

    for (int t = 0; t < T; t++) {
        const int s = t & 1;
        asm volatile("cp.async.wait_group 0;\n" ::: "memory");
        __syncthreads();   // stage s ready; all warps done with stage s^1
        if (t + 1 < T) LOAD_F16(s ^ 1, (t + 1) << 5);

        const uint32_t aS = saA + s * GSTAGE + aOff;
        const uint32_t bS = saB + s * GSTAGE + bOff;
        #pragma unroll
        for (int ks = 0; ks < 2; ks++) {
            const uint32_t kb = ks * 32;   // 16 halves = 32 B
            uint32_t af[4][4], bf[2][4];
            #pragma unroll
            for (int mi = 0; mi < 4; mi++)
                LDSM_X4(af[mi], aS + mi * (16 * 80) + kb);
            #pragma unroll
            for (int p = 0; p < 2; p++)
                LDSM_X4(bf[p], bS + p * (16 * 80) + kb);
            #pragma unroll
            for (int mi = 0; mi < 4; mi++)
                #pragma unroll
                for (int nj = 0; nj < 4; nj++)
                    mma_f16(acc[mi][nj], af[mi],
                            bf[nj >> 1][(nj & 1) * 2],
                            bf[nj >> 1][(nj & 1) * 2 + 1]);
        }
    }

    // epilogue (same layout as tf32 m16n8k8: d0,d1 row g / d2,d3 row g+8)
    #pragma unroll
    for (int mi = 0; mi < 4; mi++) {
        int row = bym + wm + mi * 16 + g;
        #pragma unroll
        for (int nj = 0; nj < 4; nj++) {
            int col = bxn + wn + nj * 8 + 2 * tig;
            float b0 = bias[col], b1 = bias[col + 1];
            float v00 = acc[mi][nj][0] + b0, v01 = acc[mi][nj][1] + b1;
            float v10 = acc[mi][nj][2] + b0, v11 = acc[mi][nj][3] + b1;
            if (round_out) {
                v00 = f2tf_f(v00); v01 = f2tf_f(v01);
                v10 = f2tf_f(v10); v11 = f2tf_f(v11);
            }
            *(float2*)&C[(size_t)row * N + col] = make_float2(v00, v01);
            *(float2*)&C[(size_t)(row + 8) * N + col] = make_float2(v10, v11);
        }
    }
}

// ---------------------------------------------------------------------------
// Fused flash attention (tf32 mma.sync, unchanged except fp16 output)
// ---------------------------------------------------------------------------
#define PS_STR 36
#define KS_STR 68
#define VS_STR 72

__global__ __launch_bounds__(256) void attn_tf32() {
    __shared__ float Ps[128][PS_STR];
    __shared__ float Ks[32][KS_STR];
    __shared__ float Vs[32][VS_STR];

    const int tid  = threadIdx.x;
    const int lane = tid & 31;
    const int w    = tid >> 5;
    const int g    = lane >> 2;
    const int tig  = lane & 3;
    const int bh   = blockIdx.y;
    const int b    = bh >> 4;
    const int h    = bh & 15;
    const int q0   = blockIdx.x * 128;
    const int row0 = w * 16 + g;

    const float* Qg = g_Q + ((size_t)(b * LQ + q0)) * HID + h * DH;
    const float* Kg = g_K + ((size_t)b * LKV) * HID + h * DH;
    const float* Vg = g_V + ((size_t)b * LKV) * HID + h * DH;
    const float* bg = g_bias + b * LKV;

    const int kr0 = tid >> 4,         kc0 = (tid & 15) * 4;
    const int kr1 = (tid + 256) >> 4, kc1 = kc0;

    uint32_t qf[8][4];
    {
        const float* q0p = Qg + (size_t)row0 * HID;
        const float* q8p = Qg + (size_t)(row0 + 8) * HID;
        #pragma unroll
        for (int kk = 0; kk < 8; kk++) {
            int col = kk * 8 + tig;
            qf[kk][0] = __float_as_uint(q0p[col]);
            qf[kk][1] = __float_as_uint(q8p[col]);
            qf[kk][2] = __float_as_uint(q0p[col + 4]);
            qf[kk][3] = __float_as_uint(q8p[col + 4]);
        }
    }

    float of[8][4];
    #pragma unroll
    for (int nj = 0; nj < 8; nj++)
        #pragma unroll
        for (int f = 0; f < 4; f++) of[nj][f] = 0.0f;
    float m0 = -1.0e30f, m1 = -1.0e30f, l0 = 0.0f, l1 = 0.0f;

    float4 kreg0, kreg1, vreg0, vreg1;
    kreg0 = *(const float4*)(Kg + (size_t)kr0 * HID + kc0);
    kreg1 = *(const float4*)(Kg + (size_t)kr1 * HID + kc1);
    vreg0 = *(const float4*)(Vg + (size_t)kr0 * HID + kc0);
    vreg1 = *(const float4*)(Vg + (size_t)kr1 * HID + kc1);

    for (int j0 = 0; j0 < LKV; j0 += 32) {
        *(float4*)&Ks[kr0][kc0] = kreg0;
        *(float4*)&Ks[kr1][kc1] = kreg1;
        *(float4*)&Vs[kr0][kc0] = vreg0;
        *(float4*)&Vs[kr1][kc1] = vreg1;
        __syncthreads();

        if (j0 + 32 < LKV) {
            const float* kn = Kg + (size_t)(j0 + 32) * HID;
            const float* vn = Vg + (size_t)(j0 + 32) * HID;
            kreg0 = *(const float4*)(kn + (size_t)kr0 * HID + kc0);
            kreg1 = *(const float4*)(kn + (size_t)kr1 * HID + kc1);
            vreg0 = *(const float4*)(vn + (size_t)kr0 * HID + kc0);
            vreg1 = *(const float4*)(vn + (size_t)kr1 * HID + kc1);
        }

        float sv[4][4];
        #pragma unroll
        for (int nj = 0; nj < 4; nj++)
            #pragma unroll
            for (int f = 0; f < 4; f++) sv[nj][f] = 0.0f;
        #pragma unroll
        for (int kk = 0; kk < 8; kk++) {
            #pragma unroll
            for (int nj = 0; nj < 4; nj++) {
                uint32_t b0 = __float_as_uint(Ks[nj * 8 + g][kk * 8 + tig]);
                uint32_t b1 = __float_as_uint(Ks[nj * 8 + g][kk * 8 + tig + 4]);
                mma_tf32(sv[nj], qf[kk], b0, b1);
            }
        }

        float mx0 = -1.0e30f, mx1 = -1.0e30f;
        #pragma unroll
        for (int nj = 0; nj < 4; nj++) {
            float2 bb = *(const float2*)&bg[j0 + nj * 8 + 2 * tig];
            sv[nj][0] = sv[nj][0] * 0.125f + bb.x;
            sv[nj][1] = sv[nj][1] * 0.125f + bb.y;
            sv[nj][2] = sv[nj][2] * 0.125f + bb.x;
            sv[nj][3] = sv[nj][3] * 0.125f + bb.y;
            mx0 = fmaxf(mx0, fmaxf(sv[nj][0], sv[nj][1]));
            mx1 = fmaxf(mx1, fmaxf(sv[nj][2], sv[nj][3]));
        }
        mx0 = fmaxf(mx0, __shfl_xor_sync(0xffffffffu, mx0, 1));
        mx0 = fmaxf(mx0, __shfl_xor_sync(0xffffffffu, mx0, 2));
        mx1 = fmaxf(mx1, __shfl_xor_sync(0xffffffffu, mx1, 1));
        mx1 = fmaxf(mx1, __shfl_xor_sync(0xffffffffu, mx1, 2));
        float mn0 = fmaxf(m0, mx0), mn1 = fmaxf(m1, mx1);
        float c0 = __expf(m0 - mn0), c1 = __expf(m1 - mn1);
        m0 = mn0; m1 = mn1;

        float sum0 = 0.0f, sum1 = 0.0f;
        #pragma unroll
        for (int nj = 0; nj < 4; nj++) {
            float p0 = __expf(sv[nj][0] - m0);
            float p1 = __expf(sv[nj][1] - m0);
            float p2 = __expf(sv[nj][2] - m1);
            float p3 = __expf(sv[nj][3] - m1);
            sum0 += p0 + p1;
            sum1 += p2 + p3;
            int col = nj * 8 + 2 * tig;
            Ps[row0][col]         = f2tf_f(p0);
            Ps[row0][col + 1]     = f2tf_f(p1);
            Ps[row0 + 8][col]     = f2tf_f(p2);
            Ps[row0 + 8][col + 1] = f2tf_f(p3);
        }
        sum0 += __shfl_xor_sync(0xffffffffu, sum0, 1);
        sum0 += __shfl_xor_sync(0xffffffffu, sum0, 2);
        sum1 += __shfl_xor_sync(0xffffffffu, sum1, 1);
        sum1 += __shfl_xor_sync(0xffffffffu, sum1, 2);
        l0 = l0 * c0 + sum0;
        l1 = l1 * c1 + sum1;

        #pragma unroll
        for (int nj = 0; nj < 8; nj++) {
            of[nj][0] *= c0; of[nj][1] *= c0;
            of[nj][2] *= c1; of[nj][3] *= c1;
        }

        __syncwarp();

        #pragma unroll
        for (int kk = 0; kk < 4; kk++) {
            uint32_t pf[4];
            int col = kk * 8 + tig;
            pf[0] = __float_as_uint(Ps[row0][col]);
            pf[1] = __float_as_uint(Ps[row0 + 8][col]);
            pf[2] = __float_as_uint(Ps[row0][col + 4]);
            pf[3] = __float_as_uint(Ps[row0 + 8][col + 4]);
            #pragma unroll
            for (int nj = 0; nj < 8; nj++) {
                uint32_t b0 = __float_as_uint(Vs[kk * 8 + tig][nj * 8 + g]);
                uint32_t b1 = __float_as_uint(Vs[kk * 8 + tig + 4][nj * 8 + g]);
                mma_tf32(of[nj], pf, b0, b1);
            }
        }
        __syncthreads();
    }

    // epilogue: divide by l, write fp16 (feeds fp16 O-proj GEMM)
    float inv0 = 1.0f / l0, inv1 = 1.0f / l1;
    #pragma unroll
    for (int nj = 0; nj < 8; nj++) {
        int col = nj * 8 + 2 * tig;
        __half* dst = &g_Oh[(size_t)(b * LQ + q0 + row0) * HID + h * DH + col];
        *(__half2*)dst = __floats2half2_rn(of[nj][0] * inv0, of[nj][1] * inv0);
        *(__half2*)(dst + (size_t)8 * HID) =
            __floats2half2_rn(of[nj][2] * inv1, of[nj][3] * inv1);
    }
}

// ---------------------------------------------------------------------------
// kernel_launch
// ---------------------------------------------------------------------------
extern "C" void kernel_launch(void* const* d_in, const int* in_sizes, int n_in,
                              void* d_out, int out_size) {
    (void)in_sizes; (void)n_in; (void)out_size;
    const float* query     = (const float*)d_in[0];
    const float* key_value = (const float*)d_in[1];
    const void*  mask      = d_in[2];
    const float* Wq = (const float*)d_in[3];
    const float* bq = (const float*)d_in[4];
    const float* Wk = (const float*)d_in[5];
    const float* bk = (const float*)d_in[6];
    const float* Wv = (const float*)d_in[7];
    const float* bv = (const float*)d_in[8];
    const float* Wo = (const float*)d_in[9];
    const float* bo = (const float*)d_in[10];
    float* out = (float*)d_out;

    float *Qp, *Kp, *Vp;
    __half *Qh, *KVh, *Oh, *WqT, *WkT, *WvT, *WoT;
    cudaGetSymbolAddress((void**)&Qp,  g_Q);
    cudaGetSymbolAddress((void**)&Kp,  g_K);
    cudaGetSymbolAddress((void**)&Vp,  g_V);
    cudaGetSymbolAddress((void**)&Qh,  g_Qh);
    cudaGetSymbolAddress((void**)&KVh, g_KVh);
    cudaGetSymbolAddress((void**)&Oh,  g_Oh);
    cudaGetSymbolAddress((void**)&WqT, g_WqT);
    cudaGetSymbolAddress((void**)&WkT, g_WkT);
    cudaGetSymbolAddress((void**)&WvT, g_WvT);
    cudaGetSymbolAddress((void**)&WoT, g_WoT);

    // mask -> additive bias
    detect_mask_kind_kernel<<<1, 256>>>((const unsigned int*)mask);
    build_bias_kernel<<<(B_ * LKV + 255) / 256, 256>>>(mask);

    // prep: fp16 activations; fp16 transposed weights [N][K]
    const int TPB = 256;
    int n4;
    n4 = (B_ * LQ * QDIM) / 4;
    to_half<<<(n4 + TPB - 1) / TPB, TPB>>>(query, Qh, n4);
    n4 = (B_ * LKV * KVDIM) / 4;
    to_half<<<(n4 + TPB - 1) / TPB, TPB>>>(key_value, KVh, n4);
    dim3 tb(32, 8);
    transpose_half<<<dim3(HID / 32, QDIM / 32), tb>>>(Wq, WqT, QDIM, HID);
    transpose_half<<<dim3(HID / 32, KVDIM / 32), tb>>>(Wk, WkT, KVDIM, HID);
    transpose_half<<<dim3(HID / 32, KVDIM / 32), tb>>>(Wv, WvT, KVDIM, HID);
    transpose_half<<<dim3(HID / 32, HID / 32), tb>>>(Wo, WoT, HID, HID);

    // projections (fp16 tensor cores, f32 accum), outputs tf32-rounded
    dim3 gq(HID / 128, (B_ * LQ) / 128);    // (8, 32)
    dim3 gkv(HID / 128, (B_ * LKV) / 128);  // (8, 128)
    gemm_f16<<<gq, 256>>>(Qh, WqT, bq, Qp, B_ * LQ, HID, QDIM, 1);
    gemm_f16<<<gkv, 256>>>(KVh, WkT, bk, Kp, B_ * LKV, HID, KVDIM, 1);
    gemm_f16<<<gkv, 256>>>(KVh, WvT, bv, Vp, B_ * LKV, HID, KVDIM, 1);

    // fused attention (tf32), writes fp16 g_Oh
    attn_tf32<<<dim3(LQ / 128, B_ * NH), 256>>>();

    // output projection (fp16 GEMM, fp32 output)
    gemm_f16<<<gq, 256>>>(Oh, WoT, bo, out, B_ * LQ, HID, HID, 0);
}

// round 13
// speedup vs baseline: 6.7557x; 1.4111x over previous
#include <cuda_runtime.h>
#include <cuda_fp16.h>
#include <math.h>
#include <stdint.h>

// Problem constants
#define B_    8
#define LQ    512
#define LKV   2048
#define QDIM  768
#define KVDIM 768
#define HID   1024
#define NH    16
#define DH    64

// ---------------------------------------------------------------------------
// Scratch (device globals)
// ---------------------------------------------------------------------------
__device__ __half g_Qp[(size_t)B_ * LQ * HID];     // projected Q (fp16)
__device__ __half g_Kp[(size_t)B_ * LKV * HID];    // projected K (fp16)
__device__ __half g_Vp[(size_t)B_ * LKV * HID];    // projected V (fp16)
__device__ __half g_Oh[(size_t)B_ * LQ * HID];     // attention out (fp16)
__device__ float  g_bias[B_ * LKV];
__device__ int    g_mask_kind;
// fp16 prep buffers
__device__ __half g_Qh[(size_t)B_ * LQ * QDIM];    // query fp16 [M][K]
__device__ __half g_KVh[(size_t)B_ * LKV * KVDIM]; // key_value fp16 [M][K]
__device__ __half g_WqT[QDIM * HID];               // W^T fp16 [N][K]
__device__ __half g_WkT[KVDIM * HID];
__device__ __half g_WvT[KVDIM * HID];
__device__ __half g_WoT[HID * HID];

// ---------------------------------------------------------------------------
// Helpers
// ---------------------------------------------------------------------------
__device__ __forceinline__ void mma_f16(float d[4], const uint32_t a[4],
                                        uint32_t b0, uint32_t b1) {
    asm volatile(
        "mma.sync.aligned.m16n8k16.row.col.f32.f16.f16.f32 "
        "{%0,%1,%2,%3}, {%4,%5,%6,%7}, {%8,%9}, {%0,%1,%2,%3};\n"
        : "+f"(d[0]), "+f"(d[1]), "+f"(d[2]), "+f"(d[3])
        : "r"(a[0]), "r"(a[1]), "r"(a[2]), "r"(a[3]), "r"(b0), "r"(b1));
}

#define LDSM_X4(r, addr)                                                      \
    asm volatile("ldmatrix.sync.aligned.m8n8.x4.shared.b16 {%0,%1,%2,%3}, [%4];" \
                 : "=r"((r)[0]), "=r"((r)[1]), "=r"((r)[2]), "=r"((r)[3])     \
                 : "r"(addr))

#define LDSM_X4_T(r, addr)                                                    \
    asm volatile("ldmatrix.sync.aligned.m8n8.x4.trans.shared.b16 {%0,%1,%2,%3}, [%4];" \
                 : "=r"((r)[0]), "=r"((r)[1]), "=r"((r)[2]), "=r"((r)[3])     \
                 : "r"(addr))

__device__ __forceinline__ void cp16(uint32_t dst_smem, const void* src) {
    asm volatile("cp.async.cg.shared.global [%0], [%1], 16;\n"
                 :: "r"(dst_smem), "l"(src));
}

__device__ __forceinline__ uint32_t smem_u32(const void* p) {
    uint32_t a;
    asm("{ .reg .u64 t; cvta.to.shared.u64 t, %1; cvt.u32.u64 %0, t; }"
        : "=r"(a) : "l"(p));
    return a;
}

__device__ __forceinline__ uint32_t ph2(float lo, float hi) {
    __half2 h = __floats2half2_rn(lo, hi);
    return *reinterpret_cast<uint32_t*>(&h);
}

// ---------------------------------------------------------------------------
// Prep kernels
// ---------------------------------------------------------------------------
__global__ void to_half(const float* __restrict__ s, __half* __restrict__ d,
                        int n4) {
    for (int i = blockIdx.x * blockDim.x + threadIdx.x; i < n4;
         i += gridDim.x * blockDim.x) {
        float4 v = ((const float4*)s)[i];
        ((__half2*)d)[i * 2]     = __floats2half2_rn(v.x, v.y);
        ((__half2*)d)[i * 2 + 1] = __floats2half2_rn(v.z, v.w);
    }
}

// W[K][N] fp32 -> WT[N][K] fp16. block (32,8), grid (N/32, K/32).
__global__ void transpose_half(const float* __restrict__ s,
                               __half* __restrict__ d, int K, int N) {
    __shared__ float t[32][33];
    int n0 = blockIdx.x * 32, k0 = blockIdx.y * 32;
    int tx = threadIdx.x, ty = threadIdx.y;
    #pragma unroll
    for (int i = 0; i < 32; i += 8)
        t[ty + i][tx] = s[(size_t)(k0 + ty + i) * N + n0 + tx];
    __syncthreads();
    #pragma unroll
    for (int i = 0; i < 32; i += 8)
        d[(size_t)(n0 + ty + i) * K + k0 + tx] = __float2half(t[tx][ty + i]);
}

// ---------------------------------------------------------------------------
// Mask dtype classification + bias build
// ---------------------------------------------------------------------------
__global__ void detect_mask_kind_kernel(const unsigned int* __restrict__ w) {
    __shared__ int bad_f32, bad_i32;
    if (threadIdx.x == 0) { bad_f32 = 0; bad_i32 = 0; }
    __syncthreads();
    int lf = 0, li = 0;
    for (int i = threadIdx.x; i < (B_ * LKV) / 4; i += blockDim.x) {
        unsigned int x = w[i];
        if (!(x == 0u || x == 0x3f800000u)) lf = 1;
        if (!(x == 0u || x == 1u))          li = 1;
    }
    if (lf) bad_f32 = 1;
    if (li) bad_i32 = 1;
    __syncthreads();
    if (threadIdx.x == 0)
        g_mask_kind = (!bad_f32) ? 0 : ((!bad_i32) ? 1 : 2);
}

__global__ void build_bias_kernel(const void* __restrict__ mp) {
    int i = blockIdx.x * blockDim.x + threadIdx.x;
    if (i >= B_ * LKV) return;
    int k = g_mask_kind;
    bool on;
    if (k == 0)      on = (((const float*)mp)[i] != 0.0f);
    else if (k == 1) on = (((const int*)mp)[i] != 0);
    else             on = (((const unsigned char*)mp)[i] != 0);
    g_bias[i] = on ? 0.0f : -1.0e30f;
}

// ---------------------------------------------------------------------------
// FP16 tensor-core GEMM:  C[M,N] = A[M,K] @ BT[N,K]^T + bias[N]  (f32 accum)
// Block 128x128, 256 threads (8 warps, 2Mx4N), warp 64x32. K-tile 32 halves.
// 2-stage cp.async, single sync/iter; ldmatrix frags, 80 B stride (64B rows).
// Exactly one of Cf / Ch is non-null: fp32 or fp16 output.
// ---------------------------------------------------------------------------
#define GSTAGE 10240   // 128 rows * 80 B

#define LOAD_F16(st, k0)                                                      \
    do {                                                                      \
        _Pragma("unroll")                                                     \
        for (int i = 0; i < 2; i++) {                                         \
            int idx = tid + i * 256;                                          \
            int r = idx >> 2, c = idx & 3;                                    \
            cp16(saA + (st) * GSTAGE + r * 80 + c * 16,                       \
                 A + (size_t)(bym + r) * K + (k0) + c * 8);                   \
            cp16(saB + (st) * GSTAGE + r * 80 + c * 16,                       \
                 BT + (size_t)(bxn + r) * K + (k0) + c * 8);                  \
        }                                                                     \
        asm volatile("cp.async.commit_group;\n" ::: "memory");                \
    } while (0)

__global__ __launch_bounds__(256, 2) void gemm_f16(
    const __half* __restrict__ A, const __half* __restrict__ BT,
    const float* __restrict__ bias, float* __restrict__ Cf,
    __half* __restrict__ Ch, int M, int N, int K)
{
    __shared__ __align__(16) __half As[2][128][40];
    __shared__ __align__(16) __half Bs[2][128][40];

    const int tid  = threadIdx.x;
    const int lane = tid & 31;
    const int wid  = tid >> 5;
    const int g    = lane >> 2;
    const int tig  = lane & 3;
    const int wm   = (wid >> 2) * 64;
    const int wn   = (wid & 3) * 32;
    const int bym  = blockIdx.y * 128;
    const int bxn  = blockIdx.x * 128;

    const uint32_t saA = smem_u32(&As[0][0][0]);
    const uint32_t saB = smem_u32(&Bs[0][0][0]);

    const int lr  = lane & 7;
    const int seg = lane >> 3;
    const uint32_t aOff = (uint32_t)(wm + lr + (seg & 1) * 8) * 80
                        + ((seg >> 1) & 1) * 16;
    const uint32_t bOff = (uint32_t)(wn + lr + ((seg >> 1) & 1) * 8) * 80
                        + (seg & 1) * 16;

    float acc[4][4][4];
    #pragma unroll
    for (int mi = 0; mi < 4; mi++)
        #pragma unroll
        for (int nj = 0; nj < 4; nj++)
            #pragma unroll
            for (int f = 0; f < 4; f++) acc[mi][nj][f] = 0.0f;

    const int T = K >> 5;
    LOAD_F16(0, 0);

    for (int t = 0; t < T; t++) {
        const int s = t & 1;
        asm volatile("cp.async.wait_group 0;\n" ::: "memory");
        __syncthreads();
        if (t + 1 < T) LOAD_F16(s ^ 1, (t + 1) << 5);

        const uint32_t aS = saA + s * GSTAGE + aOff;
        const uint32_t bS = saB + s * GSTAGE + bOff;
        #pragma unroll
        for (int ks = 0; ks < 2; ks++) {
            const uint32_t kb = ks * 32;
            uint32_t af[4][4], bf[2][4];
            #pragma unroll
            for (int mi = 0; mi < 4; mi++)
                LDSM_X4(af[mi], aS + mi * (16 * 80) + kb);
            #pragma unroll
            for (int p = 0; p < 2; p++)
                LDSM_X4(bf[p], bS + p * (16 * 80) + kb);
            #pragma unroll
            for (int mi = 0; mi < 4; mi++)
                #pragma unroll
                for (int nj = 0; nj < 4; nj++)
                    mma_f16(acc[mi][nj], af[mi],
                            bf[nj >> 1][(nj & 1) * 2],
                            bf[nj >> 1][(nj & 1) * 2 + 1]);
        }
    }

    #pragma unroll
    for (int mi = 0; mi < 4; mi++) {
        int row = bym + wm + mi * 16 + g;
        #pragma unroll
        for (int nj = 0; nj < 4; nj++) {
            int col = bxn + wn + nj * 8 + 2 * tig;
            float b0 = bias[col], b1 = bias[col + 1];
            float v00 = acc[mi][nj][0] + b0, v01 = acc[mi][nj][1] + b1;
            float v10 = acc[mi][nj][2] + b0, v11 = acc[mi][nj][3] + b1;
            if (Ch) {
                *(__half2*)&Ch[(size_t)row * N + col] =
                    __floats2half2_rn(v00, v01);
                *(__half2*)&Ch[(size_t)(row + 8) * N + col] =
                    __floats2half2_rn(v10, v11);
            } else {
                *(float2*)&Cf[(size_t)row * N + col] = make_float2(v00, v01);
                *(float2*)&Cf[(size_t)(row + 8) * N + col] =
                    make_float2(v10, v11);
            }
        }
    }
}

// ---------------------------------------------------------------------------
// Fused flash attention, fp16 mma (m16n8k16), register-resident P.
// grid = (LQ/128, B*NH), 256 threads (8 warps), warp owns 16 q-rows.
// 64-row KV tiles (d=64 -> 128 B rows), smem row stride 144 B so the 8 rows
// of every ldmatrix hit distinct 16B octants ((9r+c) mod 8 = (r+c) mod 8).
// 2-stage cp.async pipeline, one __syncthreads per tile.
// K via non-trans ldmatrix, V via ldmatrix.trans.
// Smem: 2 stages * 2 tensors * 64 * 144 B = 36864 B.
// ---------------------------------------------------------------------------
#define ASTR 144              // bytes per KV row in smem
#define ASTG (64 * ASTR)      // 9216 B per stage per tensor

#define LOAD_KV(st, j0)                                                       \
    do {                                                                      \
        _Pragma("unroll")                                                     \
        for (int i = 0; i < 2; i++) {                                         \
            int idx = tid + i * 256;                                          \
            int r = idx >> 3, c = idx & 7;                                    \
            cp16(ks0 + (st) * ASTG + r * ASTR + c * 16,                       \
                 Kg + (size_t)((j0) + r) * HID + c * 8);                      \
            cp16(vs0 + (st) * ASTG + r * ASTR + c * 16,                       \
                 Vg + (size_t)((j0) + r) * HID + c * 8);                      \
        }                                                                     \
        asm volatile("cp.async.commit_group;\n" ::: "memory");                \
    } while (0)

__global__ __launch_bounds__(256) void attn_f16() {
    __shared__ __align__(16) __half Ks[2][64][ASTR / 2];
    __shared__ __align__(16) __half Vs[2][64][ASTR / 2];

    const int tid  = threadIdx.x;
    const int lane = tid & 31;
    const int w    = tid >> 5;
    const int g    = lane >> 2;
    const int tig  = lane & 3;
    const int lr   = lane & 7;
    const int seg  = lane >> 3;
    const int bh   = blockIdx.y;
    const int b    = bh >> 4;
    const int h    = bh & 15;
    const int q0   = blockIdx.x * 128;
    const int row0 = w * 16 + g;

    const __half* Qg = g_Qp + ((size_t)(b * LQ + q0)) * HID + h * DH;
    const __half* Kg = g_Kp + ((size_t)b * LKV) * HID + h * DH;
    const __half* Vg = g_Vp + ((size_t)b * LKV) * HID + h * DH;
    const float*  bg = g_bias + b * LKV;

    const uint32_t ks0 = smem_u32(&Ks[0][0][0]);
    const uint32_t vs0 = smem_u32(&Vs[0][0][0]);

    // ldmatrix base offsets (within a stage)
    const uint32_t kOff = (uint32_t)(lr + ((seg >> 1) & 1) * 8) * ASTR
                        + (seg & 1) * 16;           // + p*(16*ASTR) + kk*32
    const uint32_t vOff = (uint32_t)(lr + (seg & 1) * 8) * ASTR
                        + ((seg >> 1) & 1) * 16;    // + kk2*(16*ASTR) + p2*32

    // ---- Q fragments from gmem fp16 (4 k-steps over d=64) ----
    uint32_t qf[4][4];
    {
        const __half* q0p = Qg + (size_t)row0 * HID;
        const __half* q8p = Qg + (size_t)(row0 + 8) * HID;
        #pragma unroll
        for (int kk = 0; kk < 4; kk++) {
            int col = kk * 16 + 2 * tig;
            qf[kk][0] = *(const uint32_t*)(q0p + col);
            qf[kk][1] = *(const uint32_t*)(q8p + col);
            qf[kk][2] = *(const uint32_t*)(q0p + col + 8);
            qf[kk][3] = *(const uint32_t*)(q8p + col + 8);
        }
    }

    float of[8][4];
    #pragma unroll
    for (int nj = 0; nj < 8; nj++)
        #pragma unroll
        for (int f = 0; f < 4; f++) of[nj][f] = 0.0f;
    float m0 = -1.0e30f, m1 = -1.0e30f, l0 = 0.0f, l1 = 0.0f;

    LOAD_KV(0, 0);

    for (int t = 0; t < LKV / 64; t++) {
        const int s  = t & 1;
        const int j0 = t * 64;
        asm volatile("cp.async.wait_group 0;\n" ::: "memory");
        __syncthreads();   // stage s ready; everyone done with stage s^1
        if (t + 1 < LKV / 64) LOAD_KV(s ^ 1, j0 + 64);

        const uint32_t kS = ks0 + s * ASTG;
        const uint32_t vS = vs0 + s * ASTG;

        // ---- S = Q K^T : rows [w*16,w*16+16) x 64 kv ----
        float sv[8][4];
        #pragma unroll
        for (int nj = 0; nj < 8; nj++)
            #pragma unroll
            for (int f = 0; f < 4; f++) sv[nj][f] = 0.0f;
        #pragma unroll
        for (int kk = 0; kk < 4; kk++) {
            #pragma unroll
            for (int p = 0; p < 4; p++) {
                uint32_t bf[4];
                LDSM_X4(bf, kS + kOff + p * (16 * ASTR) + kk * 32);
                mma_f16(sv[2 * p],     qf[kk], bf[0], bf[1]);
                mma_f16(sv[2 * p + 1], qf[kk], bf[2], bf[3]);
            }
        }

        // ---- scale + bias, online softmax in registers ----
        float mx0 = -1.0e30f, mx1 = -1.0e30f;
        #pragma unroll
        for (int nj = 0; nj < 8; nj++) {
            float2 bb = *(const float2*)&bg[j0 + nj * 8 + 2 * tig];
            sv[nj][0] = sv[nj][0] * 0.125f + bb.x;
            sv[nj][1] = sv[nj][1] * 0.125f + bb.y;
            sv[nj][2] = sv[nj][2] * 0.125f + bb.x;
            sv[nj][3] = sv[nj][3] * 0.125f + bb.y;
            mx0 = fmaxf(mx0, fmaxf(sv[nj][0], sv[nj][1]));
            mx1 = fmaxf(mx1, fmaxf(sv[nj][2], sv[nj][3]));
        }
        mx0 = fmaxf(mx0, __shfl_xor_sync(0xffffffffu, mx0, 1));
        mx0 = fmaxf(mx0, __shfl_xor_sync(0xffffffffu, mx0, 2));
        mx1 = fmaxf(mx1, __shfl_xor_sync(0xffffffffu, mx1, 1));
        mx1 = fmaxf(mx1, __shfl_xor_sync(0xffffffffu, mx1, 2));
        float mn0 = fmaxf(m0, mx0), mn1 = fmaxf(m1, mx1);
        float c0 = __expf(m0 - mn0), c1 = __expf(m1 - mn1);
        m0 = mn0; m1 = mn1;

        float sum0 = 0.0f, sum1 = 0.0f;
        #pragma unroll
        for (int nj = 0; nj < 8; nj++) {
            sv[nj][0] = __expf(sv[nj][0] - m0);
            sv[nj][1] = __expf(sv[nj][1] - m0);
            sv[nj][2] = __expf(sv[nj][2] - m1);
            sv[nj][3] = __expf(sv[nj][3] - m1);
            sum0 += sv[nj][0] + sv[nj][1];
            sum1 += sv[nj][2] + sv[nj][3];
        }
        sum0 += __shfl_xor_sync(0xffffffffu, sum0, 1);
        sum0 += __shfl_xor_sync(0xffffffffu, sum0, 2);
        sum1 += __shfl_xor_sync(0xffffffffu, sum1, 1);
        sum1 += __shfl_xor_sync(0xffffffffu, sum1, 2);
        l0 = l0 * c0 + sum0;
        l1 = l1 * c1 + sum1;

        // ---- rescale O accumulators ----
        #pragma unroll
        for (int nj = 0; nj < 8; nj++) {
            of[nj][0] *= c0; of[nj][1] *= c0;
            of[nj][2] *= c1; of[nj][3] *= c1;
        }

        // ---- O += P V : P packed straight from registers; V via trans ----
        #pragma unroll
        for (int kk2 = 0; kk2 < 4; kk2++) {
            uint32_t pf[4];
            pf[0] = ph2(sv[2 * kk2][0],     sv[2 * kk2][1]);
            pf[1] = ph2(sv[2 * kk2][2],     sv[2 * kk2][3]);
            pf[2] = ph2(sv[2 * kk2 + 1][0], sv[2 * kk2 + 1][1]);
            pf[3] = ph2(sv[2 * kk2 + 1][2], sv[2 * kk2 + 1][3]);
            #pragma unroll
            for (int p2 = 0; p2 < 4; p2++) {
                uint32_t bf[4];
                LDSM_X4_T(bf, vS + vOff + kk2 * (16 * ASTR) + p2 * 32);
                mma_f16(of[2 * p2],     pf, bf[0], bf[1]);
                mma_f16(of[2 * p2 + 1], pf, bf[2], bf[3]);
            }
        }
    }

    // ---- epilogue: divide by l, write fp16 ----
    float inv0 = 1.0f / l0, inv1 = 1.0f / l1;
    #pragma unroll
    for (int nj = 0; nj < 8; nj++) {
        int col = nj * 8 + 2 * tig;
        __half* dst = &g_Oh[(size_t)(b * LQ + q0 + row0) * HID + h * DH + col];
        *(__half2*)dst = __floats2half2_rn(of[nj][0] * inv0, of[nj][1] * inv0);
        *(__half2*)(dst + (size_t)8 * HID) =
            __floats2half2_rn(of[nj][2] * inv1, of[nj][3] * inv1);
    }
}

// ---------------------------------------------------------------------------
// kernel_launch
// ---------------------------------------------------------------------------
extern "C" void kernel_launch(void* const* d_in, const int* in_sizes, int n_in,
                              void* d_out, int out_size) {
    (void)in_sizes; (void)n_in; (void)out_size;
    const float* query     = (const float*)d_in[0];
    const float* key_value = (const float*)d_in[1];
    const void*  mask      = d_in[2];
    const float* Wq = (const float*)d_in[3];
    const float* bq = (const float*)d_in[4];
    const float* Wk = (const float*)d_in[5];
    const float* bk = (const float*)d_in[6];
    const float* Wv = (const float*)d_in[7];
    const float* bv = (const float*)d_in[8];
    const float* Wo = (const float*)d_in[9];
    const float* bo = (const float*)d_in[10];
    float* out = (float*)d_out;

    __half *Qp, *Kp, *Vp, *Qh, *KVh, *Oh, *WqT, *WkT, *WvT, *WoT;
    cudaGetSymbolAddress((void**)&Qp,  g_Qp);
    cudaGetSymbolAddress((void**)&Kp,  g_Kp);
    cudaGetSymbolAddress((void**)&Vp,  g_Vp);
    cudaGetSymbolAddress((void**)&Qh,  g_Qh);
    cudaGetSymbolAddress((void**)&KVh, g_KVh);
    cudaGetSymbolAddress((void**)&Oh,  g_Oh);
    cudaGetSymbolAddress((void**)&WqT, g_WqT);
    cudaGetSymbolAddress((void**)&WkT, g_WkT);
    cudaGetSymbolAddress((void**)&WvT, g_WvT);
    cudaGetSymbolAddress((void**)&WoT, g_WoT);

    // mask -> additive bias
    detect_mask_kind_kernel<<<1, 256>>>((const unsigned int*)mask);
    build_bias_kernel<<<(B_ * LKV + 255) / 256, 256>>>(mask);

    // prep: fp16 activations; fp16 transposed weights [N][K]
    const int TPB = 256;
    int n4;
    n4 = (B_ * LQ * QDIM) / 4;
    to_half<<<(n4 + TPB - 1) / TPB, TPB>>>(query, Qh, n4);
    n4 = (B_ * LKV * KVDIM) / 4;
    to_half<<<(n4 + TPB - 1) / TPB, TPB>>>(key_value, KVh, n4);
    dim3 tb(32, 8);
    transpose_half<<<dim3(HID / 32, QDIM / 32), tb>>>(Wq, WqT, QDIM, HID);
    transpose_half<<<dim3(HID / 32, KVDIM / 32), tb>>>(Wk, WkT, KVDIM, HID);
    transpose_half<<<dim3(HID / 32, KVDIM / 32), tb>>>(Wv, WvT, KVDIM, HID);
    transpose_half<<<dim3(HID / 32, HID / 32), tb>>>(Wo, WoT, HID, HID);

    // projections (fp16 tensor cores, f32 accum) -> fp16 outputs
    dim3 gq(HID / 128, (B_ * LQ) / 128);    // (8, 32)
    dim3 gkv(HID / 128, (B_ * LKV) / 128);  // (8, 128)
    gemm_f16<<<gq, 256>>>(Qh, WqT, bq, nullptr, Qp, B_ * LQ, HID, QDIM);
    gemm_f16<<<gkv, 256>>>(KVh, WkT, bk, nullptr, Kp, B_ * LKV, HID, KVDIM);
    gemm_f16<<<gkv, 256>>>(KVh, WvT, bv, nullptr, Vp, B_ * LKV, HID, KVDIM);

    // fused attention (fp16 mma, register P)
    attn_f16<<<dim3(LQ / 128, B_ * NH), 256>>>();

    // output projection (fp16 GEMM, fp32 output)
    gemm_f16<<<gq, 256>>>(Oh, WoT, bo, out, nullptr, B_ * LQ, HID, HID);
}